// round 11
// baseline (speedup 1.0000x reference)
#include <cuda_runtime.h>
#include <cuda_bf16.h>
#include <math.h>
#include <stdint.h>

#define BB 4
#define LL 2048
#define DD 1024
#define HH 16
#define HDD 64
#define NTOK (BB*LL)            // 8192 rows
#define NEL  (BB*HH*LL*HDD)     // 8.4M elements

// Scratch (device globals — no allocations allowed)
__device__ float g_Q[NEL];      // fp32 head-major pre-LN
__device__ float g_K[NEL];
__device__ __align__(16) __nv_bfloat16 g_xh[NEL],  g_xl[NEL];     // x split
__device__ __align__(16) __nv_bfloat16 g_Wqh[DD*DD], g_Wql[DD*DD];
__device__ __align__(16) __nv_bfloat16 g_Wkh[DD*DD], g_Wkl[DD*DD];
__device__ __align__(16) __nv_bfloat16 g_Wvh[DD*DD], g_Wvl[DD*DD];
__device__ __align__(16) __nv_bfloat16 g_Woh[DD*DD], g_Wol[DD*DD];
__device__ __align__(16) __nv_bfloat16 g_Qh[NEL], g_Ql[NEL];
__device__ __align__(16) __nv_bfloat16 g_Kh[NEL], g_Kl[NEL];
__device__ __align__(16) __nv_bfloat16 g_Vh[NEL], g_Vl[NEL];
__device__ __align__(16) __nv_bfloat16 g_Ch[NEL], g_Cl[NEL];      // ctx split

// ===========================================================================
// helpers
// ===========================================================================
__device__ __forceinline__ uint32_t smem_u32(const void* p) {
    uint32_t a;
    asm("{ .reg .u64 t; cvta.to.shared.u64 t, %1; cvt.u32.u64 %0, t; }"
        : "=r"(a) : "l"(p));
    return a;
}

__device__ __forceinline__ void mma_bf16(float* c, const uint32_t* a, const uint32_t* b) {
    asm volatile(
        "mma.sync.aligned.m16n8k16.row.col.f32.bf16.bf16.f32 "
        "{%0,%1,%2,%3}, {%4,%5,%6,%7}, {%8,%9}, {%0,%1,%2,%3};"
        : "+f"(c[0]), "+f"(c[1]), "+f"(c[2]), "+f"(c[3])
        : "r"(a[0]), "r"(a[1]), "r"(a[2]), "r"(a[3]), "r"(b[0]), "r"(b[1]));
}

__device__ __forceinline__ void ldmx4(uint32_t* r, uint32_t addr) {
    asm volatile("ldmatrix.sync.aligned.m8n8.x4.shared.b16 {%0,%1,%2,%3}, [%4];"
                 : "=r"(r[0]), "=r"(r[1]), "=r"(r[2]), "=r"(r[3]) : "r"(addr));
}
__device__ __forceinline__ void ldmx4t(uint32_t* r, uint32_t addr) {
    asm volatile("ldmatrix.sync.aligned.m8n8.x4.trans.shared.b16 {%0,%1,%2,%3}, [%4];"
                 : "=r"(r[0]), "=r"(r[1]), "=r"(r[2]), "=r"(r[3]) : "r"(addr));
}

__device__ __forceinline__ void cp16(uint32_t dst, const void* src) {
    asm volatile("cp.async.cg.shared.global [%0], [%1], 16;" :: "r"(dst), "l"(src));
}
#define CP_COMMIT() asm volatile("cp.async.commit_group;" ::: "memory")
#define CP_WAIT1()  asm volatile("cp.async.wait_group 1;" ::: "memory")

// split two floats into packed bf16 hi + bf16 lo (residual)
__device__ __forceinline__ void split2(float a, float b, uint32_t& h, uint32_t& l) {
    __nv_bfloat16 ha = __float2bfloat16_rn(a);
    __nv_bfloat16 hb = __float2bfloat16_rn(b);
    float ra = a - __bfloat162float(ha);
    float rb = b - __bfloat162float(hb);
    __nv_bfloat162 hv; hv.x = ha; hv.y = hb;
    __nv_bfloat162 lv = __floats2bfloat162_rn(ra, rb);
    h = *(uint32_t*)&hv;
    l = *(uint32_t*)&lv;
}

// fast 2^t on FMA/ALU pipes (no MUFU). clamped at -100; t <= ~12 here.
__device__ __forceinline__ float exp2p(float t) {
    t = fmaxf(t, -100.0f);
    float z = t + 12582912.0f;
    float f = t - (z - 12582912.0f);
    float p =             1.3333558e-3f;
    p = fmaf(p, f, 9.6181291e-3f);
    p = fmaf(p, f, 5.5504109e-2f);
    p = fmaf(p, f, 2.4022651e-1f);
    p = fmaf(p, f, 6.9314718e-1f);
    p = fmaf(p, f, 1.0f);
    return __int_as_float(__float_as_int(p) + (__float_as_int(z) << 23));
}

// ---------------------------------------------------------------------------
// fp32 -> bf16 hi/lo splitters
// ---------------------------------------------------------------------------
__global__ __launch_bounds__(256) void split_f32(const float* __restrict__ X,
                                                 __nv_bfloat16* __restrict__ Xh,
                                                 __nv_bfloat16* __restrict__ Xl)
{
    int i = blockIdx.x * 256 + threadIdx.x;
    float4 v = ((const float4*)X)[i];
    uint32_t h0, l0, h1, l1;
    split2(v.x, v.y, h0, l0);
    split2(v.z, v.w, h1, l1);
    ((uint2*)Xh)[i] = make_uint2(h0, h1);
    ((uint2*)Xl)[i] = make_uint2(l0, l1);
}

// all four weight matrices in one launch: blockIdx.x>>10 selects the matrix
__global__ __launch_bounds__(256) void split_w4(const float* __restrict__ W0,
                                                const float* __restrict__ W1,
                                                const float* __restrict__ W2,
                                                const float* __restrict__ W3,
                                                __nv_bfloat16* __restrict__ H0,
                                                __nv_bfloat16* __restrict__ L0,
                                                __nv_bfloat16* __restrict__ H1,
                                                __nv_bfloat16* __restrict__ L1,
                                                __nv_bfloat16* __restrict__ H2,
                                                __nv_bfloat16* __restrict__ L2,
                                                __nv_bfloat16* __restrict__ H3,
                                                __nv_bfloat16* __restrict__ L3)
{
    int which = blockIdx.x >> 10;
    int i = (blockIdx.x & 1023) * 256 + threadIdx.x;
    const float* W = which == 0 ? W0 : which == 1 ? W1 : which == 2 ? W2 : W3;
    __nv_bfloat16* H = which == 0 ? H0 : which == 1 ? H1 : which == 2 ? H2 : H3;
    __nv_bfloat16* L = which == 0 ? L0 : which == 1 ? L1 : which == 2 ? L2 : L3;
    float4 v = ((const float4*)W)[i];
    uint32_t h0, l0, h1, l1;
    split2(v.x, v.y, h0, l0);
    split2(v.z, v.w, h1, l1);
    ((uint2*)H)[i] = make_uint2(h0, h1);
    ((uint2*)L)[i] = make_uint2(l0, l1);
}

// ===========================================================================
// bf16x3 GEMM on pre-split operands: C[M,1024] = A @ B^T
// CTA 128x128, BK=32, 8 warps (2x4). Buffer = {Ah,Al,Bh,Bl} x 8KB = 32KB;
// double-buffered = 64KB/CTA -> 2 CTAs per SM (the R10 profile showed
// tensor=61% at 1 CTA/SM; this is the occupancy fix).
// Swizzle (64B rows, 16B chunks): ch ^= (row>>1)&3  (verified R5 layout).
// ===========================================================================
#define GBUF 32768

__global__ __launch_bounds__(256, 2) void gemm_bs(const __nv_bfloat16* __restrict__ Ah,
                                                  const __nv_bfloat16* __restrict__ Al,
                                                  const __nv_bfloat16* __restrict__ Bh,
                                                  const __nv_bfloat16* __restrict__ Bl,
                                                  float* __restrict__ C,
                                                  __nv_bfloat16* __restrict__ Ch,
                                                  __nv_bfloat16* __restrict__ Cl,
                                                  int mode)
{
    extern __shared__ char gsm[];
    const uint32_t smb = smem_u32(gsm);
    const int tid  = threadIdx.x;
    const int lane = tid & 31;
    const int wid  = tid >> 5;
    const int wm0  = (wid & 1) * 64;
    const int wn0  = (wid >> 1) * 32;
    const int m0   = blockIdx.y * 128;
    const int n0   = blockIdx.x * 128;
    const int mat  = lane >> 3;

    float acc[4][4][4] = {};

    // prefetch k-chunk kc (32 wide) into buffer b:
    // 4 tiles x 128 rows x 4 chunks of 16B = 2048 chunks / 256 thr = 8 each
    auto prefetch = [&](int kc, int b) {
        const __nv_bfloat16* srcs[4] = { Ah, Al, Bh, Bl };
        #pragma unroll
        for (int j = 0; j < 8; j++) {
            const int tile = j >> 1;
            int c   = (j & 1) * 256 + tid;       // 0..511
            int row = c >> 2, ch = c & 3;
            int grow = (tile < 2 ? m0 : n0) + row;
            const __nv_bfloat16* src = srcs[tile] + (size_t)grow * DD + kc * 32 + ch * 8;
            uint32_t dst = smb + b * GBUF + tile * 8192 + row * 64
                         + ((ch ^ ((row >> 1) & 3)) << 4);
            cp16(dst, src);
        }
    };

    prefetch(0, 0);
    CP_COMMIT();

    for (int kc = 0; kc < 32; kc++) {
        const int buf = kc & 1;
        if (kc + 1 < 32) prefetch(kc + 1, buf ^ 1);
        CP_COMMIT();
        CP_WAIT1();
        __syncthreads();

        const uint32_t bAh = smb + buf * GBUF;
        const uint32_t bAl = bAh + 8192;
        const uint32_t bBh = bAh + 16384;
        const uint32_t bBl = bAh + 24576;

        #pragma unroll
        for (int ks = 0; ks < 2; ks++) {
            uint32_t aH[4][4], aL[4][4];
            #pragma unroll
            for (int mt = 0; mt < 4; mt++) {
                int r  = wm0 + mt * 16 + ((mat & 1) << 3) + (lane & 7);
                int ch = 2 * ks + (mat >> 1);
                uint32_t off = r * 64 + ((ch ^ ((r >> 1) & 3)) << 4);
                ldmx4(aH[mt], bAh + off);
                ldmx4(aL[mt], bAl + off);
            }
            uint32_t bH[2][4], bL[2][4];
            #pragma unroll
            for (int np = 0; np < 2; np++) {
                int rn = wn0 + np * 16 + ((mat >> 1) << 3) + (lane & 7);
                int ch = 2 * ks + (mat & 1);
                uint32_t off = rn * 64 + ((ch ^ ((rn >> 1) & 3)) << 4);
                ldmx4(bH[np], bBh + off);
                ldmx4(bL[np], bBl + off);
            }
            #pragma unroll
            for (int mt = 0; mt < 4; mt++)
                #pragma unroll
                for (int np = 0; np < 2; np++) {
                    mma_bf16(acc[mt][2*np],   aH[mt], bH[np]);
                    mma_bf16(acc[mt][2*np],   aH[mt], bL[np]);
                    mma_bf16(acc[mt][2*np],   aL[mt], bH[np]);
                    mma_bf16(acc[mt][2*np+1], aH[mt], bH[np] + 2);
                    mma_bf16(acc[mt][2*np+1], aH[mt], bL[np] + 2);
                    mma_bf16(acc[mt][2*np+1], aL[mt], bH[np] + 2);
                }
        }
        __syncthreads();
    }

    #pragma unroll
    for (int mt = 0; mt < 4; mt++) {
        #pragma unroll
        for (int nt = 0; nt < 4; nt++) {
            int row = m0 + wm0 + mt * 16 + (lane >> 2);
            int col = n0 + wn0 + nt * 8 + ((lane & 3) << 1);
            #pragma unroll
            for (int hf = 0; hf < 2; hf++) {
                int r = row + hf * 8;
                float2 v = make_float2(acc[mt][nt][2*hf], acc[mt][nt][2*hf + 1]);
                if (mode == 0) {
                    *(float2*)&C[(size_t)r * DD + col] = v;
                } else {
                    int bI = r >> 11, l = r & (LL - 1);
                    int hh = col >> 6, hd = col & 63;
                    size_t off = ((size_t)((bI * HH + hh) * LL + l) << 6) + hd;
                    if (mode == 1) {
                        *(float2*)&C[off] = v;
                    } else {
                        uint32_t vh, vl;
                        split2(v.x, v.y, vh, vl);
                        *(uint32_t*)&Ch[off] = vh;
                        *(uint32_t*)&Cl[off] = vl;
                    }
                }
            }
        }
    }
}

// ---------------------------------------------------------------------------
// Per-head LayerNorm over HD=64, fp32 in -> bf16 hi/lo out, scale folded.
// ---------------------------------------------------------------------------
__global__ __launch_bounds__(256) void ln_head_split(const float* __restrict__ X,
                                                     const float* __restrict__ gamma,
                                                     const float* __restrict__ beta,
                                                     __nv_bfloat16* __restrict__ Xh,
                                                     __nv_bfloat16* __restrict__ Xl,
                                                     float scale)
{
    int row  = blockIdx.x * 8 + (threadIdx.x >> 5);
    int lane = threadIdx.x & 31;
    float2 v = *(const float2*)&X[(size_t)row * 64 + lane * 2];
    float s  = v.x + v.y;
    float sq = v.x * v.x + v.y * v.y;
    #pragma unroll
    for (int off = 16; off > 0; off >>= 1) {
        s  += __shfl_xor_sync(0xffffffffu, s,  off);
        sq += __shfl_xor_sync(0xffffffffu, sq, off);
    }
    float mean = s * (1.0f / 64.0f);
    float var  = sq * (1.0f / 64.0f) - mean * mean;
    float inv  = rsqrtf(var + 1e-5f);
    float g0 = gamma[lane * 2] * scale, g1 = gamma[lane * 2 + 1] * scale;
    float b0 = beta[lane * 2] * scale,  b1 = beta[lane * 2 + 1] * scale;
    v.x = (v.x - mean) * (inv * g0) + b0;
    v.y = (v.y - mean) * (inv * g1) + b1;
    uint32_t h, l;
    split2(v.x, v.y, h, l);
    *(uint32_t*)&Xh[(size_t)row * 64 + lane * 2] = h;
    *(uint32_t*)&Xl[(size_t)row * 64 + lane * 2] = l;
}

// ===========================================================================
// Tensor-core causal flash attention. 8 warps x 16 Q-rows, BK=128. (R10)
// ===========================================================================
#define CS 0.18033688f   // 0.125 * log2(e)
#define FBUF 65536       // bytes per flash buffer

__global__ __launch_bounds__(256, 1) void flash_mma(
    const __nv_bfloat16* __restrict__ Qh, const __nv_bfloat16* __restrict__ Ql,
    const __nv_bfloat16* __restrict__ Kh, const __nv_bfloat16* __restrict__ Kl,
    const __nv_bfloat16* __restrict__ Vh, const __nv_bfloat16* __restrict__ Vl,
    __nv_bfloat16* __restrict__ ctxh, __nv_bfloat16* __restrict__ ctxl)
{
    extern __shared__ char fsm[];
    const uint32_t smb = smem_u32(fsm);
    const int tid  = threadIdx.x;
    const int lane = tid & 31;
    const int w    = tid >> 5;
    const int bh   = blockIdx.x;
    const int qt   = (gridDim.y - 1) - blockIdx.y;   // heavy CTAs first

    const __nv_bfloat16* Qhg = Qh + (size_t)bh * LL * HDD;
    const __nv_bfloat16* Qlg = Ql + (size_t)bh * LL * HDD;
    const __nv_bfloat16* Khg = Kh + (size_t)bh * LL * HDD;
    const __nv_bfloat16* Klg = Kl + (size_t)bh * LL * HDD;
    const __nv_bfloat16* Vhg = Vh + (size_t)bh * LL * HDD;
    const __nv_bfloat16* Vlg = Vl + (size_t)bh * LL * HDD;

    const int wq = qt * 128 + w * 16;

    // ---- Q fragments (bf16 hi/lo, pre-scaled by CS in LN) ----
    uint32_t Qah[4][4], Qal[4][4];
    {
        int ra = wq + (lane >> 2);
        #pragma unroll
        for (int ks = 0; ks < 4; ks++) {
            int d0 = ks * 16 + (lane & 3) * 2;
            Qah[ks][0] = *(const uint32_t*)&Qhg[(size_t)ra * 64 + d0];
            Qah[ks][1] = *(const uint32_t*)&Qhg[(size_t)(ra + 8) * 64 + d0];
            Qah[ks][2] = *(const uint32_t*)&Qhg[(size_t)ra * 64 + d0 + 8];
            Qah[ks][3] = *(const uint32_t*)&Qhg[(size_t)(ra + 8) * 64 + d0 + 8];
            Qal[ks][0] = *(const uint32_t*)&Qlg[(size_t)ra * 64 + d0];
            Qal[ks][1] = *(const uint32_t*)&Qlg[(size_t)(ra + 8) * 64 + d0];
            Qal[ks][2] = *(const uint32_t*)&Qlg[(size_t)ra * 64 + d0 + 8];
            Qal[ks][3] = *(const uint32_t*)&Qlg[(size_t)(ra + 8) * 64 + d0 + 8];
        }
    }

    float o[8][4] = {};
    float l0 = 0.0f, l1 = 0.0f;      // lane-local partial row sums

    const int nkt    = qt + 1;                 // 128-key tiles
    const int my_nkt = ((wq + 15) >> 7) + 1;   // warp-level skip of masked tiles

    auto prefetch = [&](int kt, int bufb) {
        #pragma unroll
        for (int j = 0; j < 16; j++) {
            const int tile = j >> 2;
            int c   = (j & 3) * 256 + tid;       // 0..1023
            int row = c >> 3, ch = c & 7;
            const __nv_bfloat16* src =
                (tile == 0 ? Khg : tile == 1 ? Klg : tile == 2 ? Vhg : Vlg)
                + (size_t)(kt * 128 + row) * 64 + ch * 8;
            uint32_t dst = smb + bufb * FBUF + tile * 16384 + row * 128
                         + ((ch ^ (row & 7)) << 4);
            cp16(dst, src);
        }
    };

    prefetch(0, 0);
    CP_COMMIT();

    for (int kt = 0; kt < nkt; kt++) {
        const int buf = kt & 1;
        if (kt + 1 < nkt) prefetch(kt + 1, buf ^ 1);
        CP_COMMIT();
        CP_WAIT1();
        __syncthreads();

        if (kt < my_nkt) {
            const uint32_t bKh = smb + buf * FBUF;
            const uint32_t bKl = bKh + 16384;
            const uint32_t bVh = bKh + 32768;
            const uint32_t bVl = bKh + 49152;

            // ---- S = Q K^T (bf16x3), S already in log2 scale ----
            float s[16][4] = {};
            #pragma unroll
            for (int ks = 0; ks < 4; ks++) {
                #pragma unroll
                for (int ntp = 0; ntp < 8; ntp++) {
                    int mat  = lane >> 3;
                    int key  = ntp * 16 + (mat >> 1) * 8 + (lane & 7);
                    int ch   = 2 * ks + (mat & 1);
                    uint32_t off = key * 128 + (((ch ^ (key & 7))) << 4);
                    uint32_t kh[4], kl[4];
                    ldmx4(kh, bKh + off);
                    ldmx4(kl, bKl + off);
                    mma_bf16(s[2*ntp],   Qah[ks], kh);
                    mma_bf16(s[2*ntp],   Qah[ks], kl);
                    mma_bf16(s[2*ntp],   Qal[ks], kh);
                    mma_bf16(s[2*ntp+1], Qah[ks], kh + 2);
                    mma_bf16(s[2*ntp+1], Qah[ks], kl + 2);
                    mma_bf16(s[2*ntp+1], Qal[ks], kh + 2);
                }
            }

            // ---- causal mask (only near-diagonal tiles) ----
            if ((kt << 7) + 127 > wq) {
                int q0 = wq + (lane >> 2), q1 = q0 + 8;
                #pragma unroll
                for (int nt = 0; nt < 16; nt++) {
                    int key = (kt << 7) + nt * 8 + ((lane & 3) << 1);
                    if (key     > q0) s[nt][0] = -1e30f;
                    if (key + 1 > q0) s[nt][1] = -1e30f;
                    if (key     > q1) s[nt][2] = -1e30f;
                    if (key + 1 > q1) s[nt][3] = -1e30f;
                }
            }

            // ---- p = exp2(s), lane-local sums ----
            #pragma unroll
            for (int nt = 0; nt < 16; nt++) {
                float p0 = exp2p(s[nt][0]);
                float p1 = exp2p(s[nt][1]);
                float p2 = exp2p(s[nt][2]);
                float p3 = exp2p(s[nt][3]);
                s[nt][0] = p0; s[nt][1] = p1; s[nt][2] = p2; s[nt][3] = p3;
                l0 += p0 + p1;
                l1 += p2 + p3;
            }

            // ---- O += P V ----
            #pragma unroll
            for (int ks = 0; ks < 8; ks++) {
                uint32_t Ph[4], Pl[4];
                split2(s[2*ks][0],   s[2*ks][1],   Ph[0], Pl[0]);
                split2(s[2*ks][2],   s[2*ks][3],   Ph[1], Pl[1]);
                split2(s[2*ks+1][0], s[2*ks+1][1], Ph[2], Pl[2]);
                split2(s[2*ks+1][2], s[2*ks+1][3], Ph[3], Pl[3]);
                #pragma unroll
                for (int ntp = 0; ntp < 4; ntp++) {
                    int mat = lane >> 3;
                    int kk  = ks * 16 + (mat & 1) * 8 + (lane & 7);
                    int ch  = ntp * 2 + (mat >> 1);
                    uint32_t off = kk * 128 + (((ch ^ (kk & 7))) << 4);
                    uint32_t vh[4], vl[4];
                    ldmx4t(vh, bVh + off);
                    ldmx4t(vl, bVl + off);
                    mma_bf16(o[2*ntp],   Ph, vh);
                    mma_bf16(o[2*ntp],   Ph, vl);
                    mma_bf16(o[2*ntp],   Pl, vh);
                    mma_bf16(o[2*ntp+1], Ph, vh + 2);
                    mma_bf16(o[2*ntp+1], Ph, vl + 2);
                    mma_bf16(o[2*ntp+1], Pl, vh + 2);
                }
            }
        }
        __syncthreads();
    }

    // ---- single deferred row-sum reduction ----
    l0 += __shfl_xor_sync(0xffffffffu, l0, 1);
    l0 += __shfl_xor_sync(0xffffffffu, l0, 2);
    l1 += __shfl_xor_sync(0xffffffffu, l1, 1);
    l1 += __shfl_xor_sync(0xffffffffu, l1, 2);

    // ---- epilogue: normalize, split, write ctx hi/lo [b,l,d] ----
    const int b = bh >> 4, hdh = bh & 15;
    const int q0 = wq + (lane >> 2), q1 = q0 + 8;
    float inv0 = 1.0f / l0, inv1 = 1.0f / l1;
    #pragma unroll
    for (int nt = 0; nt < 8; nt++) {
        int d = nt * 8 + ((lane & 3) << 1);
        size_t o0 = (size_t)(b * LL + q0) * DD + hdh * 64 + d;
        size_t o1 = (size_t)(b * LL + q1) * DD + hdh * 64 + d;
        uint32_t vh, vl;
        split2(o[nt][0] * inv0, o[nt][1] * inv0, vh, vl);
        *(uint32_t*)&ctxh[o0] = vh;
        *(uint32_t*)&ctxl[o0] = vl;
        split2(o[nt][2] * inv1, o[nt][3] * inv1, vh, vl);
        *(uint32_t*)&ctxh[o1] = vh;
        *(uint32_t*)&ctxl[o1] = vl;
    }
}

// ---------------------------------------------------------------------------
extern "C" void kernel_launch(void* const* d_in, const int* in_sizes, int n_in,
                              void* d_out, int out_size)
{
    const float* x      = (const float*)d_in[0];
    // d_in[1] = causal mask (tril) — causality applied analytically, unused
    const float* Wq     = (const float*)d_in[2];
    const float* Wk     = (const float*)d_in[3];
    const float* Wv     = (const float*)d_in[4];
    const float* Wo     = (const float*)d_in[5];
    const float* qgamma = (const float*)d_in[6];
    const float* qbeta  = (const float*)d_in[7];
    const float* kgamma = (const float*)d_in[8];
    const float* kbeta  = (const float*)d_in[9];
    float* out = (float*)d_out;

    float *dQ, *dK;
    __nv_bfloat16 *dxh, *dxl, *dQh, *dQl, *dKh, *dKl, *dVh, *dVl, *dCh, *dCl;
    __nv_bfloat16 *dWqh, *dWql, *dWkh, *dWkl, *dWvh, *dWvl, *dWoh, *dWol;
    cudaGetSymbolAddress((void**)&dQ,  g_Q);
    cudaGetSymbolAddress((void**)&dK,  g_K);
    cudaGetSymbolAddress((void**)&dxh, g_xh);   cudaGetSymbolAddress((void**)&dxl, g_xl);
    cudaGetSymbolAddress((void**)&dQh, g_Qh);   cudaGetSymbolAddress((void**)&dQl, g_Ql);
    cudaGetSymbolAddress((void**)&dKh, g_Kh);   cudaGetSymbolAddress((void**)&dKl, g_Kl);
    cudaGetSymbolAddress((void**)&dVh, g_Vh);   cudaGetSymbolAddress((void**)&dVl, g_Vl);
    cudaGetSymbolAddress((void**)&dCh, g_Ch);   cudaGetSymbolAddress((void**)&dCl, g_Cl);
    cudaGetSymbolAddress((void**)&dWqh, g_Wqh); cudaGetSymbolAddress((void**)&dWql, g_Wql);
    cudaGetSymbolAddress((void**)&dWkh, g_Wkh); cudaGetSymbolAddress((void**)&dWkl, g_Wkl);
    cudaGetSymbolAddress((void**)&dWvh, g_Wvh); cudaGetSymbolAddress((void**)&dWvl, g_Wvl);
    cudaGetSymbolAddress((void**)&dWoh, g_Woh); cudaGetSymbolAddress((void**)&dWol, g_Wol);

    const int gemm_smem  = 2 * GBUF;   // 64 KB
    const int flash_smem = 2 * FBUF;   // 128 KB
    cudaFuncSetAttribute(gemm_bs,
                         cudaFuncAttributeMaxDynamicSharedMemorySize, gemm_smem);
    cudaFuncSetAttribute(flash_mma,
                         cudaFuncAttributeMaxDynamicSharedMemorySize, flash_smem);

    // operand pre-splits
    split_f32<<<NEL / 1024, 256>>>(x, dxh, dxl);
    split_w4<<<4 * (DD * DD / 1024), 256>>>(Wq, Wk, Wv, Wo,
                                            dWqh, dWql, dWkh, dWkl,
                                            dWvh, dWvl, dWoh, dWol);

    dim3 gg(DD / 128, NTOK / 128);   // (8, 64)

    gemm_bs<<<gg, 256, gemm_smem>>>(dxh, dxl, dWqh, dWql, dQ, nullptr, nullptr, 1);
    gemm_bs<<<gg, 256, gemm_smem>>>(dxh, dxl, dWkh, dWkl, dK, nullptr, nullptr, 1);
    gemm_bs<<<gg, 256, gemm_smem>>>(dxh, dxl, dWvh, dWvl, nullptr, dVh, dVl, 2);

    ln_head_split<<<(BB * HH * LL) / 8, 256>>>(dQ, qgamma, qbeta, dQh, dQl, CS);
    ln_head_split<<<(BB * HH * LL) / 8, 256>>>(dK, kgamma, kbeta, dKh, dKl, 1.0f);

    flash_mma<<<dim3(BB * HH, LL / 128), 256, flash_smem>>>(dQh, dQl, dKh, dKl,
                                                            dVh, dVl, dCh, dCl);

    gemm_bs<<<gg, 256, gemm_smem>>>(dCh, dCl, dWoh, dWol, out, nullptr, nullptr, 0);
}

// round 12
// speedup vs baseline: 1.1052x; 1.1052x over previous
#include <cuda_runtime.h>
#include <cuda_bf16.h>
#include <math.h>
#include <stdint.h>

#define BB 4
#define LL 2048
#define DD 1024
#define HH 16
#define HDD 64
#define NTOK (BB*LL)            // 8192 rows
#define NEL  (BB*HH*LL*HDD)     // 8.4M elements

// Scratch (device globals — no allocations allowed)
__device__ float g_Q[NEL];      // fp32 head-major pre-LN
__device__ float g_K[NEL];
__device__ __align__(16) __nv_bfloat16 g_xh[NEL],  g_xl[NEL];     // x split
__device__ __align__(16) __nv_bfloat16 g_Wqh[DD*DD], g_Wql[DD*DD];
__device__ __align__(16) __nv_bfloat16 g_Wkh[DD*DD], g_Wkl[DD*DD];
__device__ __align__(16) __nv_bfloat16 g_Wvh[DD*DD], g_Wvl[DD*DD];
__device__ __align__(16) __nv_bfloat16 g_Woh[DD*DD], g_Wol[DD*DD];
__device__ __align__(16) __nv_bfloat16 g_Qh[NEL], g_Ql[NEL];
__device__ __align__(16) __nv_bfloat16 g_Kh[NEL], g_Kl[NEL];
__device__ __align__(16) __nv_bfloat16 g_Vh[NEL], g_Vl[NEL];
__device__ __align__(16) __nv_bfloat16 g_Ch[NEL], g_Cl[NEL];      // ctx split

// ===========================================================================
// helpers
// ===========================================================================
__device__ __forceinline__ uint32_t smem_u32(const void* p) {
    uint32_t a;
    asm("{ .reg .u64 t; cvta.to.shared.u64 t, %1; cvt.u32.u64 %0, t; }"
        : "=r"(a) : "l"(p));
    return a;
}

__device__ __forceinline__ void mma_bf16(float* c, const uint32_t* a, const uint32_t* b) {
    asm volatile(
        "mma.sync.aligned.m16n8k16.row.col.f32.bf16.bf16.f32 "
        "{%0,%1,%2,%3}, {%4,%5,%6,%7}, {%8,%9}, {%0,%1,%2,%3};"
        : "+f"(c[0]), "+f"(c[1]), "+f"(c[2]), "+f"(c[3])
        : "r"(a[0]), "r"(a[1]), "r"(a[2]), "r"(a[3]), "r"(b[0]), "r"(b[1]));
}

__device__ __forceinline__ void ldmx4(uint32_t* r, uint32_t addr) {
    asm volatile("ldmatrix.sync.aligned.m8n8.x4.shared.b16 {%0,%1,%2,%3}, [%4];"
                 : "=r"(r[0]), "=r"(r[1]), "=r"(r[2]), "=r"(r[3]) : "r"(addr));
}
__device__ __forceinline__ void ldmx4t(uint32_t* r, uint32_t addr) {
    asm volatile("ldmatrix.sync.aligned.m8n8.x4.trans.shared.b16 {%0,%1,%2,%3}, [%4];"
                 : "=r"(r[0]), "=r"(r[1]), "=r"(r[2]), "=r"(r[3]) : "r"(addr));
}

__device__ __forceinline__ void cp16(uint32_t dst, const void* src) {
    asm volatile("cp.async.cg.shared.global [%0], [%1], 16;" :: "r"(dst), "l"(src));
}
#define CP_COMMIT() asm volatile("cp.async.commit_group;" ::: "memory")
#define CP_WAIT1()  asm volatile("cp.async.wait_group 1;" ::: "memory")

// split two floats into packed bf16 hi + bf16 lo (residual)
__device__ __forceinline__ void split2(float a, float b, uint32_t& h, uint32_t& l) {
    __nv_bfloat16 ha = __float2bfloat16_rn(a);
    __nv_bfloat16 hb = __float2bfloat16_rn(b);
    float ra = a - __bfloat162float(ha);
    float rb = b - __bfloat162float(hb);
    __nv_bfloat162 hv; hv.x = ha; hv.y = hb;
    __nv_bfloat162 lv = __floats2bfloat162_rn(ra, rb);
    h = *(uint32_t*)&hv;
    l = *(uint32_t*)&lv;
}

// fast 2^t on FMA/ALU pipes (no MUFU). clamped at -100; t <= ~12 here.
__device__ __forceinline__ float exp2p(float t) {
    t = fmaxf(t, -100.0f);
    float z = t + 12582912.0f;
    float f = t - (z - 12582912.0f);
    float p =             1.3333558e-3f;
    p = fmaf(p, f, 9.6181291e-3f);
    p = fmaf(p, f, 5.5504109e-2f);
    p = fmaf(p, f, 2.4022651e-1f);
    p = fmaf(p, f, 6.9314718e-1f);
    p = fmaf(p, f, 1.0f);
    return __int_as_float(__float_as_int(p) + (__float_as_int(z) << 23));
}

// ---------------------------------------------------------------------------
// fp32 -> bf16 hi/lo splitters
// ---------------------------------------------------------------------------
__global__ __launch_bounds__(256) void split_f32(const float* __restrict__ X,
                                                 __nv_bfloat16* __restrict__ Xh,
                                                 __nv_bfloat16* __restrict__ Xl)
{
    int i = blockIdx.x * 256 + threadIdx.x;
    float4 v = ((const float4*)X)[i];
    uint32_t h0, l0, h1, l1;
    split2(v.x, v.y, h0, l0);
    split2(v.z, v.w, h1, l1);
    ((uint2*)Xh)[i] = make_uint2(h0, h1);
    ((uint2*)Xl)[i] = make_uint2(l0, l1);
}

// all four weight matrices in one launch: blockIdx.x>>10 selects the matrix
__global__ __launch_bounds__(256) void split_w4(const float* __restrict__ W0,
                                                const float* __restrict__ W1,
                                                const float* __restrict__ W2,
                                                const float* __restrict__ W3,
                                                __nv_bfloat16* __restrict__ H0,
                                                __nv_bfloat16* __restrict__ L0,
                                                __nv_bfloat16* __restrict__ H1,
                                                __nv_bfloat16* __restrict__ L1,
                                                __nv_bfloat16* __restrict__ H2,
                                                __nv_bfloat16* __restrict__ L2,
                                                __nv_bfloat16* __restrict__ H3,
                                                __nv_bfloat16* __restrict__ L3)
{
    int which = blockIdx.x >> 10;
    int i = (blockIdx.x & 1023) * 256 + threadIdx.x;
    const float* W = which == 0 ? W0 : which == 1 ? W1 : which == 2 ? W2 : W3;
    __nv_bfloat16* H = which == 0 ? H0 : which == 1 ? H1 : which == 2 ? H2 : H3;
    __nv_bfloat16* L = which == 0 ? L0 : which == 1 ? L1 : which == 2 ? L2 : L3;
    float4 v = ((const float4*)W)[i];
    uint32_t h0, l0, h1, l1;
    split2(v.x, v.y, h0, l0);
    split2(v.z, v.w, h1, l1);
    ((uint2*)H)[i] = make_uint2(h0, h1);
    ((uint2*)L)[i] = make_uint2(l0, l1);
}

// ===========================================================================
// bf16x3 GEMM on pre-split operands: C[M,1024] = A @ B^T
// CTA 128x128, BK=32, **4 warps of 64x64** (128 threads).
// Per kstep/warp: 16 LDSM.x4 feed 96 HMMA (ratio 6 vs 4 before) — attacks
// the 61%-tensor LDSM/MIO feed ceiling seen in R10/R11.
// Buffer = {Ah,Al,Bh,Bl} x 8KB = 32KB; double-buffered 64KB/CTA -> 2 CTA/SM.
// launch_bounds(128,2): 256 regs/thread available, ~220 live.
// ===========================================================================
#define GBUF 32768

__global__ __launch_bounds__(128, 2) void gemm_bs(const __nv_bfloat16* __restrict__ Ah,
                                                  const __nv_bfloat16* __restrict__ Al,
                                                  const __nv_bfloat16* __restrict__ Bh,
                                                  const __nv_bfloat16* __restrict__ Bl,
                                                  float* __restrict__ C,
                                                  __nv_bfloat16* __restrict__ Ch,
                                                  __nv_bfloat16* __restrict__ Cl,
                                                  int mode)
{
    extern __shared__ char gsm[];
    const uint32_t smb = smem_u32(gsm);
    const int tid  = threadIdx.x;
    const int lane = tid & 31;
    const int wid  = tid >> 5;
    const int wm0  = (wid & 1) * 64;    // 2 warps along M
    const int wn0  = (wid >> 1) * 64;   // 2 warps along N, 64 wide each
    const int m0   = blockIdx.y * 128;
    const int n0   = blockIdx.x * 128;
    const int mat  = lane >> 3;

    float acc[4][8][4] = {};            // [mt][nt(8 wide)][frag]

    // prefetch k-chunk kc (32 wide) into buffer b:
    // 4 tiles x 128 rows x 4 chunks of 16B = 2048 chunks / 128 thr = 16 each
    auto prefetch = [&](int kc, int b) {
        const __nv_bfloat16* srcs[4] = { Ah, Al, Bh, Bl };
        #pragma unroll
        for (int j = 0; j < 16; j++) {
            const int tile = j >> 2;
            int c   = (j & 3) * 128 + tid;       // 0..511
            int row = c >> 2, ch = c & 3;
            int grow = (tile < 2 ? m0 : n0) + row;
            const __nv_bfloat16* src = srcs[tile] + (size_t)grow * DD + kc * 32 + ch * 8;
            uint32_t dst = smb + b * GBUF + tile * 8192 + row * 64
                         + ((ch ^ ((row >> 1) & 3)) << 4);
            cp16(dst, src);
        }
    };

    prefetch(0, 0);
    CP_COMMIT();

    for (int kc = 0; kc < 32; kc++) {
        const int buf = kc & 1;
        if (kc + 1 < 32) prefetch(kc + 1, buf ^ 1);
        CP_COMMIT();
        CP_WAIT1();
        __syncthreads();

        const uint32_t bAh = smb + buf * GBUF;
        const uint32_t bAl = bAh + 8192;
        const uint32_t bBh = bAh + 16384;
        const uint32_t bBl = bAh + 24576;

        #pragma unroll
        for (int ks = 0; ks < 2; ks++) {
            uint32_t aH[4][4], aL[4][4];
            #pragma unroll
            for (int mt = 0; mt < 4; mt++) {
                int r  = wm0 + mt * 16 + ((mat & 1) << 3) + (lane & 7);
                int ch = 2 * ks + (mat >> 1);
                uint32_t off = r * 64 + ((ch ^ ((r >> 1) & 3)) << 4);
                ldmx4(aH[mt], bAh + off);
                ldmx4(aL[mt], bAl + off);
            }
            uint32_t bH[4][4], bL[4][4];
            #pragma unroll
            for (int np = 0; np < 4; np++) {
                int rn = wn0 + np * 16 + ((mat >> 1) << 3) + (lane & 7);
                int ch = 2 * ks + (mat & 1);
                uint32_t off = rn * 64 + ((ch ^ ((rn >> 1) & 3)) << 4);
                ldmx4(bH[np], bBh + off);
                ldmx4(bL[np], bBl + off);
            }
            #pragma unroll
            for (int mt = 0; mt < 4; mt++)
                #pragma unroll
                for (int np = 0; np < 4; np++) {
                    mma_bf16(acc[mt][2*np],   aH[mt], bH[np]);
                    mma_bf16(acc[mt][2*np],   aH[mt], bL[np]);
                    mma_bf16(acc[mt][2*np],   aL[mt], bH[np]);
                    mma_bf16(acc[mt][2*np+1], aH[mt], bH[np] + 2);
                    mma_bf16(acc[mt][2*np+1], aH[mt], bL[np] + 2);
                    mma_bf16(acc[mt][2*np+1], aL[mt], bH[np] + 2);
                }
        }
        __syncthreads();
    }

    #pragma unroll
    for (int mt = 0; mt < 4; mt++) {
        #pragma unroll
        for (int nt = 0; nt < 8; nt++) {
            int row = m0 + wm0 + mt * 16 + (lane >> 2);
            int col = n0 + wn0 + nt * 8 + ((lane & 3) << 1);
            #pragma unroll
            for (int hf = 0; hf < 2; hf++) {
                int r = row + hf * 8;
                float2 v = make_float2(acc[mt][nt][2*hf], acc[mt][nt][2*hf + 1]);
                if (mode == 0) {
                    *(float2*)&C[(size_t)r * DD + col] = v;
                } else {
                    int bI = r >> 11, l = r & (LL - 1);
                    int hh = col >> 6, hd = col & 63;
                    size_t off = ((size_t)((bI * HH + hh) * LL + l) << 6) + hd;
                    if (mode == 1) {
                        *(float2*)&C[off] = v;
                    } else {
                        uint32_t vh, vl;
                        split2(v.x, v.y, vh, vl);
                        *(uint32_t*)&Ch[off] = vh;
                        *(uint32_t*)&Cl[off] = vl;
                    }
                }
            }
        }
    }
}

// ---------------------------------------------------------------------------
// Per-head LayerNorm over HD=64, fp32 in -> bf16 hi/lo out, scale folded.
// ---------------------------------------------------------------------------
__global__ __launch_bounds__(256) void ln_head_split(const float* __restrict__ X,
                                                     const float* __restrict__ gamma,
                                                     const float* __restrict__ beta,
                                                     __nv_bfloat16* __restrict__ Xh,
                                                     __nv_bfloat16* __restrict__ Xl,
                                                     float scale)
{
    int row  = blockIdx.x * 8 + (threadIdx.x >> 5);
    int lane = threadIdx.x & 31;
    float2 v = *(const float2*)&X[(size_t)row * 64 + lane * 2];
    float s  = v.x + v.y;
    float sq = v.x * v.x + v.y * v.y;
    #pragma unroll
    for (int off = 16; off > 0; off >>= 1) {
        s  += __shfl_xor_sync(0xffffffffu, s,  off);
        sq += __shfl_xor_sync(0xffffffffu, sq, off);
    }
    float mean = s * (1.0f / 64.0f);
    float var  = sq * (1.0f / 64.0f) - mean * mean;
    float inv  = rsqrtf(var + 1e-5f);
    float g0 = gamma[lane * 2] * scale, g1 = gamma[lane * 2 + 1] * scale;
    float b0 = beta[lane * 2] * scale,  b1 = beta[lane * 2 + 1] * scale;
    v.x = (v.x - mean) * (inv * g0) + b0;
    v.y = (v.y - mean) * (inv * g1) + b1;
    uint32_t h, l;
    split2(v.x, v.y, h, l);
    *(uint32_t*)&Xh[(size_t)row * 64 + lane * 2] = h;
    *(uint32_t*)&Xl[(size_t)row * 64 + lane * 2] = l;
}

// ===========================================================================
// Tensor-core causal flash attention. 8 warps x 16 Q-rows, BK=128. (R10)
// ===========================================================================
#define CS 0.18033688f   // 0.125 * log2(e)
#define FBUF 65536       // bytes per flash buffer

__global__ __launch_bounds__(256, 1) void flash_mma(
    const __nv_bfloat16* __restrict__ Qh, const __nv_bfloat16* __restrict__ Ql,
    const __nv_bfloat16* __restrict__ Kh, const __nv_bfloat16* __restrict__ Kl,
    const __nv_bfloat16* __restrict__ Vh, const __nv_bfloat16* __restrict__ Vl,
    __nv_bfloat16* __restrict__ ctxh, __nv_bfloat16* __restrict__ ctxl)
{
    extern __shared__ char fsm[];
    const uint32_t smb = smem_u32(fsm);
    const int tid  = threadIdx.x;
    const int lane = tid & 31;
    const int w    = tid >> 5;
    const int bh   = blockIdx.x;
    const int qt   = (gridDim.y - 1) - blockIdx.y;   // heavy CTAs first

    const __nv_bfloat16* Qhg = Qh + (size_t)bh * LL * HDD;
    const __nv_bfloat16* Qlg = Ql + (size_t)bh * LL * HDD;
    const __nv_bfloat16* Khg = Kh + (size_t)bh * LL * HDD;
    const __nv_bfloat16* Klg = Kl + (size_t)bh * LL * HDD;
    const __nv_bfloat16* Vhg = Vh + (size_t)bh * LL * HDD;
    const __nv_bfloat16* Vlg = Vl + (size_t)bh * LL * HDD;

    const int wq = qt * 128 + w * 16;

    // ---- Q fragments (bf16 hi/lo, pre-scaled by CS in LN) ----
    uint32_t Qah[4][4], Qal[4][4];
    {
        int ra = wq + (lane >> 2);
        #pragma unroll
        for (int ks = 0; ks < 4; ks++) {
            int d0 = ks * 16 + (lane & 3) * 2;
            Qah[ks][0] = *(const uint32_t*)&Qhg[(size_t)ra * 64 + d0];
            Qah[ks][1] = *(const uint32_t*)&Qhg[(size_t)(ra + 8) * 64 + d0];
            Qah[ks][2] = *(const uint32_t*)&Qhg[(size_t)ra * 64 + d0 + 8];
            Qah[ks][3] = *(const uint32_t*)&Qhg[(size_t)(ra + 8) * 64 + d0 + 8];
            Qal[ks][0] = *(const uint32_t*)&Qlg[(size_t)ra * 64 + d0];
            Qal[ks][1] = *(const uint32_t*)&Qlg[(size_t)(ra + 8) * 64 + d0];
            Qal[ks][2] = *(const uint32_t*)&Qlg[(size_t)ra * 64 + d0 + 8];
            Qal[ks][3] = *(const uint32_t*)&Qlg[(size_t)(ra + 8) * 64 + d0 + 8];
        }
    }

    float o[8][4] = {};
    float l0 = 0.0f, l1 = 0.0f;      // lane-local partial row sums

    const int nkt    = qt + 1;                 // 128-key tiles
    const int my_nkt = ((wq + 15) >> 7) + 1;   // warp-level skip of masked tiles

    auto prefetch = [&](int kt, int bufb) {
        #pragma unroll
        for (int j = 0; j < 16; j++) {
            const int tile = j >> 2;
            int c   = (j & 3) * 256 + tid;       // 0..1023
            int row = c >> 3, ch = c & 7;
            const __nv_bfloat16* src =
                (tile == 0 ? Khg : tile == 1 ? Klg : tile == 2 ? Vhg : Vlg)
                + (size_t)(kt * 128 + row) * 64 + ch * 8;
            uint32_t dst = smb + bufb * FBUF + tile * 16384 + row * 128
                         + ((ch ^ (row & 7)) << 4);
            cp16(dst, src);
        }
    };

    prefetch(0, 0);
    CP_COMMIT();

    for (int kt = 0; kt < nkt; kt++) {
        const int buf = kt & 1;
        if (kt + 1 < nkt) prefetch(kt + 1, buf ^ 1);
        CP_COMMIT();
        CP_WAIT1();
        __syncthreads();

        if (kt < my_nkt) {
            const uint32_t bKh = smb + buf * FBUF;
            const uint32_t bKl = bKh + 16384;
            const uint32_t bVh = bKh + 32768;
            const uint32_t bVl = bKh + 49152;

            // ---- S = Q K^T (bf16x3), S already in log2 scale ----
            float s[16][4] = {};
            #pragma unroll
            for (int ks = 0; ks < 4; ks++) {
                #pragma unroll
                for (int ntp = 0; ntp < 8; ntp++) {
                    int mat  = lane >> 3;
                    int key  = ntp * 16 + (mat >> 1) * 8 + (lane & 7);
                    int ch   = 2 * ks + (mat & 1);
                    uint32_t off = key * 128 + (((ch ^ (key & 7))) << 4);
                    uint32_t kh[4], kl[4];
                    ldmx4(kh, bKh + off);
                    ldmx4(kl, bKl + off);
                    mma_bf16(s[2*ntp],   Qah[ks], kh);
                    mma_bf16(s[2*ntp],   Qah[ks], kl);
                    mma_bf16(s[2*ntp],   Qal[ks], kh);
                    mma_bf16(s[2*ntp+1], Qah[ks], kh + 2);
                    mma_bf16(s[2*ntp+1], Qah[ks], kl + 2);
                    mma_bf16(s[2*ntp+1], Qal[ks], kh + 2);
                }
            }

            // ---- causal mask (only near-diagonal tiles) ----
            if ((kt << 7) + 127 > wq) {
                int q0 = wq + (lane >> 2), q1 = q0 + 8;
                #pragma unroll
                for (int nt = 0; nt < 16; nt++) {
                    int key = (kt << 7) + nt * 8 + ((lane & 3) << 1);
                    if (key     > q0) s[nt][0] = -1e30f;
                    if (key + 1 > q0) s[nt][1] = -1e30f;
                    if (key     > q1) s[nt][2] = -1e30f;
                    if (key + 1 > q1) s[nt][3] = -1e30f;
                }
            }

            // ---- p = exp2(s), lane-local sums ----
            #pragma unroll
            for (int nt = 0; nt < 16; nt++) {
                float p0 = exp2p(s[nt][0]);
                float p1 = exp2p(s[nt][1]);
                float p2 = exp2p(s[nt][2]);
                float p3 = exp2p(s[nt][3]);
                s[nt][0] = p0; s[nt][1] = p1; s[nt][2] = p2; s[nt][3] = p3;
                l0 += p0 + p1;
                l1 += p2 + p3;
            }

            // ---- O += P V ----
            #pragma unroll
            for (int ks = 0; ks < 8; ks++) {
                uint32_t Ph[4], Pl[4];
                split2(s[2*ks][0],   s[2*ks][1],   Ph[0], Pl[0]);
                split2(s[2*ks][2],   s[2*ks][3],   Ph[1], Pl[1]);
                split2(s[2*ks+1][0], s[2*ks+1][1], Ph[2], Pl[2]);
                split2(s[2*ks+1][2], s[2*ks+1][3], Ph[3], Pl[3]);
                #pragma unroll
                for (int ntp = 0; ntp < 4; ntp++) {
                    int mat = lane >> 3;
                    int kk  = ks * 16 + (mat & 1) * 8 + (lane & 7);
                    int ch  = ntp * 2 + (mat >> 1);
                    uint32_t off = kk * 128 + (((ch ^ (kk & 7))) << 4);
                    uint32_t vh[4], vl[4];
                    ldmx4t(vh, bVh + off);
                    ldmx4t(vl, bVl + off);
                    mma_bf16(o[2*ntp],   Ph, vh);
                    mma_bf16(o[2*ntp],   Ph, vl);
                    mma_bf16(o[2*ntp],   Pl, vh);
                    mma_bf16(o[2*ntp+1], Ph, vh + 2);
                    mma_bf16(o[2*ntp+1], Ph, vl + 2);
                    mma_bf16(o[2*ntp+1], Pl, vh + 2);
                }
            }
        }
        __syncthreads();
    }

    // ---- single deferred row-sum reduction ----
    l0 += __shfl_xor_sync(0xffffffffu, l0, 1);
    l0 += __shfl_xor_sync(0xffffffffu, l0, 2);
    l1 += __shfl_xor_sync(0xffffffffu, l1, 1);
    l1 += __shfl_xor_sync(0xffffffffu, l1, 2);

    // ---- epilogue: normalize, split, write ctx hi/lo [b,l,d] ----
    const int b = bh >> 4, hdh = bh & 15;
    const int q0 = wq + (lane >> 2), q1 = q0 + 8;
    float inv0 = 1.0f / l0, inv1 = 1.0f / l1;
    #pragma unroll
    for (int nt = 0; nt < 8; nt++) {
        int d = nt * 8 + ((lane & 3) << 1);
        size_t o0 = (size_t)(b * LL + q0) * DD + hdh * 64 + d;
        size_t o1 = (size_t)(b * LL + q1) * DD + hdh * 64 + d;
        uint32_t vh, vl;
        split2(o[nt][0] * inv0, o[nt][1] * inv0, vh, vl);
        *(uint32_t*)&ctxh[o0] = vh;
        *(uint32_t*)&ctxl[o0] = vl;
        split2(o[nt][2] * inv1, o[nt][3] * inv1, vh, vl);
        *(uint32_t*)&ctxh[o1] = vh;
        *(uint32_t*)&ctxl[o1] = vl;
    }
}

// ---------------------------------------------------------------------------
extern "C" void kernel_launch(void* const* d_in, const int* in_sizes, int n_in,
                              void* d_out, int out_size)
{
    const float* x      = (const float*)d_in[0];
    // d_in[1] = causal mask (tril) — causality applied analytically, unused
    const float* Wq     = (const float*)d_in[2];
    const float* Wk     = (const float*)d_in[3];
    const float* Wv     = (const float*)d_in[4];
    const float* Wo     = (const float*)d_in[5];
    const float* qgamma = (const float*)d_in[6];
    const float* qbeta  = (const float*)d_in[7];
    const float* kgamma = (const float*)d_in[8];
    const float* kbeta  = (const float*)d_in[9];
    float* out = (float*)d_out;

    float *dQ, *dK;
    __nv_bfloat16 *dxh, *dxl, *dQh, *dQl, *dKh, *dKl, *dVh, *dVl, *dCh, *dCl;
    __nv_bfloat16 *dWqh, *dWql, *dWkh, *dWkl, *dWvh, *dWvl, *dWoh, *dWol;
    cudaGetSymbolAddress((void**)&dQ,  g_Q);
    cudaGetSymbolAddress((void**)&dK,  g_K);
    cudaGetSymbolAddress((void**)&dxh, g_xh);   cudaGetSymbolAddress((void**)&dxl, g_xl);
    cudaGetSymbolAddress((void**)&dQh, g_Qh);   cudaGetSymbolAddress((void**)&dQl, g_Ql);
    cudaGetSymbolAddress((void**)&dKh, g_Kh);   cudaGetSymbolAddress((void**)&dKl, g_Kl);
    cudaGetSymbolAddress((void**)&dVh, g_Vh);   cudaGetSymbolAddress((void**)&dVl, g_Vl);
    cudaGetSymbolAddress((void**)&dCh, g_Ch);   cudaGetSymbolAddress((void**)&dCl, g_Cl);
    cudaGetSymbolAddress((void**)&dWqh, g_Wqh); cudaGetSymbolAddress((void**)&dWql, g_Wql);
    cudaGetSymbolAddress((void**)&dWkh, g_Wkh); cudaGetSymbolAddress((void**)&dWkl, g_Wkl);
    cudaGetSymbolAddress((void**)&dWvh, g_Wvh); cudaGetSymbolAddress((void**)&dWvl, g_Wvl);
    cudaGetSymbolAddress((void**)&dWoh, g_Woh); cudaGetSymbolAddress((void**)&dWol, g_Wol);

    const int gemm_smem  = 2 * GBUF;   // 64 KB
    const int flash_smem = 2 * FBUF;   // 128 KB
    cudaFuncSetAttribute(gemm_bs,
                         cudaFuncAttributeMaxDynamicSharedMemorySize, gemm_smem);
    cudaFuncSetAttribute(flash_mma,
                         cudaFuncAttributeMaxDynamicSharedMemorySize, flash_smem);

    // operand pre-splits
    split_f32<<<NEL / 1024, 256>>>(x, dxh, dxl);
    split_w4<<<4 * (DD * DD / 1024), 256>>>(Wq, Wk, Wv, Wo,
                                            dWqh, dWql, dWkh, dWkl,
                                            dWvh, dWvl, dWoh, dWol);

    dim3 gg(DD / 128, NTOK / 128);   // (8, 64)

    gemm_bs<<<gg, 128, gemm_smem>>>(dxh, dxl, dWqh, dWql, dQ, nullptr, nullptr, 1);
    gemm_bs<<<gg, 128, gemm_smem>>>(dxh, dxl, dWkh, dWkl, dK, nullptr, nullptr, 1);
    gemm_bs<<<gg, 128, gemm_smem>>>(dxh, dxl, dWvh, dWvl, nullptr, dVh, dVl, 2);

    ln_head_split<<<(BB * HH * LL) / 8, 256>>>(dQ, qgamma, qbeta, dQh, dQl, CS);
    ln_head_split<<<(BB * HH * LL) / 8, 256>>>(dK, kgamma, kbeta, dKh, dKl, 1.0f);

    flash_mma<<<dim3(BB * HH, LL / 128), 256, flash_smem>>>(dQh, dQl, dKh, dKl,
                                                            dVh, dVl, dCh, dCl);

    gemm_bs<<<gg, 128, gemm_smem>>>(dCh, dCl, dWoh, dWol, out, nullptr, nullptr, 0);
}

// round 13
// speedup vs baseline: 1.6924x; 1.5314x over previous
#include <cuda_runtime.h>
#include <cuda_bf16.h>
#include <cuda_fp16.h>
#include <math.h>
#include <stdint.h>

#define BB 4
#define LL 2048
#define DD 1024
#define HH 16
#define HDD 64
#define NTOK (BB*LL)            // 8192 rows
#define NEL  (BB*HH*LL*HDD)     // 8.4M elements

// Scratch (device globals — no allocations allowed)
__device__ float g_Q[NEL];      // fp32 head-major pre-LN
__device__ float g_K[NEL];
__device__ __align__(16) __half g_xf[NEL];          // x fp16
__device__ __align__(16) __half g_Wq16[DD*DD], g_Wk16[DD*DD];
__device__ __align__(16) __half g_Wv16[DD*DD], g_Wo16[DD*DD];
__device__ __align__(16) __half g_Cf[NEL];          // ctx fp16
__device__ __align__(16) __nv_bfloat16 g_Qh[NEL], g_Ql[NEL];
__device__ __align__(16) __nv_bfloat16 g_Kh[NEL], g_Kl[NEL];
__device__ __align__(16) __nv_bfloat16 g_Vh[NEL], g_Vl[NEL];

// ===========================================================================
// helpers
// ===========================================================================
__device__ __forceinline__ uint32_t smem_u32(const void* p) {
    uint32_t a;
    asm("{ .reg .u64 t; cvta.to.shared.u64 t, %1; cvt.u32.u64 %0, t; }"
        : "=r"(a) : "l"(p));
    return a;
}

__device__ __forceinline__ void mma_bf16(float* c, const uint32_t* a, const uint32_t* b) {
    asm volatile(
        "mma.sync.aligned.m16n8k16.row.col.f32.bf16.bf16.f32 "
        "{%0,%1,%2,%3}, {%4,%5,%6,%7}, {%8,%9}, {%0,%1,%2,%3};"
        : "+f"(c[0]), "+f"(c[1]), "+f"(c[2]), "+f"(c[3])
        : "r"(a[0]), "r"(a[1]), "r"(a[2]), "r"(a[3]), "r"(b[0]), "r"(b[1]));
}

__device__ __forceinline__ void mma_fp16(float* c, const uint32_t* a, const uint32_t* b) {
    asm volatile(
        "mma.sync.aligned.m16n8k16.row.col.f32.f16.f16.f32 "
        "{%0,%1,%2,%3}, {%4,%5,%6,%7}, {%8,%9}, {%0,%1,%2,%3};"
        : "+f"(c[0]), "+f"(c[1]), "+f"(c[2]), "+f"(c[3])
        : "r"(a[0]), "r"(a[1]), "r"(a[2]), "r"(a[3]), "r"(b[0]), "r"(b[1]));
}

__device__ __forceinline__ void ldmx4(uint32_t* r, uint32_t addr) {
    asm volatile("ldmatrix.sync.aligned.m8n8.x4.shared.b16 {%0,%1,%2,%3}, [%4];"
                 : "=r"(r[0]), "=r"(r[1]), "=r"(r[2]), "=r"(r[3]) : "r"(addr));
}
__device__ __forceinline__ void ldmx4t(uint32_t* r, uint32_t addr) {
    asm volatile("ldmatrix.sync.aligned.m8n8.x4.trans.shared.b16 {%0,%1,%2,%3}, [%4];"
                 : "=r"(r[0]), "=r"(r[1]), "=r"(r[2]), "=r"(r[3]) : "r"(addr));
}

__device__ __forceinline__ void cp16(uint32_t dst, const void* src) {
    asm volatile("cp.async.cg.shared.global [%0], [%1], 16;" :: "r"(dst), "l"(src));
}
#define CP_COMMIT() asm volatile("cp.async.commit_group;" ::: "memory")
#define CP_WAIT1()  asm volatile("cp.async.wait_group 1;" ::: "memory")

// split two floats into packed bf16 hi + bf16 lo (residual)
__device__ __forceinline__ void split2(float a, float b, uint32_t& h, uint32_t& l) {
    __nv_bfloat16 ha = __float2bfloat16_rn(a);
    __nv_bfloat16 hb = __float2bfloat16_rn(b);
    float ra = a - __bfloat162float(ha);
    float rb = b - __bfloat162float(hb);
    __nv_bfloat162 hv; hv.x = ha; hv.y = hb;
    __nv_bfloat162 lv = __floats2bfloat162_rn(ra, rb);
    h = *(uint32_t*)&hv;
    l = *(uint32_t*)&lv;
}

// fast 2^t on FMA/ALU pipes (no MUFU). clamped at -100; t <= ~12 here.
__device__ __forceinline__ float exp2p(float t) {
    t = fmaxf(t, -100.0f);
    float z = t + 12582912.0f;
    float f = t - (z - 12582912.0f);
    float p =             1.3333558e-3f;
    p = fmaf(p, f, 9.6181291e-3f);
    p = fmaf(p, f, 5.5504109e-2f);
    p = fmaf(p, f, 2.4022651e-1f);
    p = fmaf(p, f, 6.9314718e-1f);
    p = fmaf(p, f, 1.0f);
    return __int_as_float(__float_as_int(p) + (__float_as_int(z) << 23));
}

// ---------------------------------------------------------------------------
// fp32 -> fp16 converters
// ---------------------------------------------------------------------------
__global__ __launch_bounds__(256) void tohalf(const float* __restrict__ X,
                                              __half* __restrict__ Y)
{
    int i = blockIdx.x * 256 + threadIdx.x;
    float4 v = ((const float4*)X)[i];
    __half2 a = __floats2half2_rn(v.x, v.y);
    __half2 b = __floats2half2_rn(v.z, v.w);
    ((uint2*)Y)[i] = make_uint2(*(uint32_t*)&a, *(uint32_t*)&b);
}

// all four weight matrices in one launch: blockIdx.x>>10 selects the matrix
__global__ __launch_bounds__(256) void tohalf_w4(const float* __restrict__ W0,
                                                 const float* __restrict__ W1,
                                                 const float* __restrict__ W2,
                                                 const float* __restrict__ W3,
                                                 __half* __restrict__ Y0,
                                                 __half* __restrict__ Y1,
                                                 __half* __restrict__ Y2,
                                                 __half* __restrict__ Y3)
{
    int which = blockIdx.x >> 10;
    int i = (blockIdx.x & 1023) * 256 + threadIdx.x;
    const float* W = which == 0 ? W0 : which == 1 ? W1 : which == 2 ? W2 : W3;
    __half* Y = which == 0 ? Y0 : which == 1 ? Y1 : which == 2 ? Y2 : Y3;
    float4 v = ((const float4*)W)[i];
    __half2 a = __floats2half2_rn(v.x, v.y);
    __half2 b = __floats2half2_rn(v.z, v.w);
    ((uint2*)Y)[i] = make_uint2(*(uint32_t*)&a, *(uint32_t*)&b);
}

// ===========================================================================
// fp16 single-mma GEMM: C[M,1024] = A @ B^T
// CTA 128x128, BK=64, 4 warps of 64x64 (128 threads).
// Per kstep/warp: 8 LDSM.x4 feed 32 HMMA. 3x fewer mma + 2x fewer LDSM
// than the bf16x3 version. fp16 (11-bit mantissa) keeps per-GEMM rel err
// ~2e-4 (<< 1e-3 gate).
// Buffer = {A,B} x 16KB = 32KB; double-buffered 64KB/CTA -> 2 CTA/SM.
// Rows 128B, swizzle: ch ^= row&7 (8 chunks of 16B).
// mode 0: fp32 row-major; 1: fp32 head-major; 2: bf16 hi/lo head-major (V).
// ===========================================================================
#define GBUF 32768

__global__ __launch_bounds__(128, 2) void gemm_fp16(const __half* __restrict__ A,
                                                    const __half* __restrict__ B,
                                                    float* __restrict__ C,
                                                    __nv_bfloat16* __restrict__ Ch,
                                                    __nv_bfloat16* __restrict__ Cl,
                                                    int mode)
{
    extern __shared__ char gsm[];
    const uint32_t smb = smem_u32(gsm);
    const int tid  = threadIdx.x;
    const int lane = tid & 31;
    const int wid  = tid >> 5;
    const int wm0  = (wid & 1) * 64;
    const int wn0  = (wid >> 1) * 64;
    const int m0   = blockIdx.y * 128;
    const int n0   = blockIdx.x * 128;
    const int mat  = lane >> 3;

    float acc[4][8][4] = {};

    // prefetch k-chunk kc (64 wide) into buffer b:
    // 2 tiles x 128 rows x 8 chunks of 16B = 2048 chunks / 128 thr = 16 each
    auto prefetch = [&](int kc, int b) {
        #pragma unroll
        for (int j = 0; j < 16; j++) {
            const int tile = j >> 3;
            int c   = (j & 7) * 128 + tid;       // 0..1023
            int row = c >> 3, ch = c & 7;
            int grow = (tile == 0 ? m0 : n0) + row;
            const __half* src = (tile == 0 ? A : B) + (size_t)grow * DD + kc * 64 + ch * 8;
            uint32_t dst = smb + b * GBUF + tile * 16384 + row * 128
                         + ((ch ^ (row & 7)) << 4);
            cp16(dst, src);
        }
    };

    prefetch(0, 0);
    CP_COMMIT();

    for (int kc = 0; kc < 16; kc++) {
        const int buf = kc & 1;
        if (kc + 1 < 16) prefetch(kc + 1, buf ^ 1);
        CP_COMMIT();
        CP_WAIT1();
        __syncthreads();

        const uint32_t bA = smb + buf * GBUF;
        const uint32_t bB = bA + 16384;

        #pragma unroll
        for (int ks = 0; ks < 4; ks++) {
            uint32_t aF[4][4];
            #pragma unroll
            for (int mt = 0; mt < 4; mt++) {
                int r  = wm0 + mt * 16 + ((mat & 1) << 3) + (lane & 7);
                int ch = 2 * ks + (mat >> 1);
                uint32_t off = r * 128 + ((ch ^ (r & 7)) << 4);
                ldmx4(aF[mt], bA + off);
            }
            uint32_t bF[4][4];
            #pragma unroll
            for (int np = 0; np < 4; np++) {
                int rn = wn0 + np * 16 + ((mat >> 1) << 3) + (lane & 7);
                int ch = 2 * ks + (mat & 1);
                uint32_t off = rn * 128 + ((ch ^ (rn & 7)) << 4);
                ldmx4(bF[np], bB + off);
            }
            #pragma unroll
            for (int mt = 0; mt < 4; mt++)
                #pragma unroll
                for (int np = 0; np < 4; np++) {
                    mma_fp16(acc[mt][2*np],   aF[mt], bF[np]);
                    mma_fp16(acc[mt][2*np+1], aF[mt], bF[np] + 2);
                }
        }
        __syncthreads();
    }

    #pragma unroll
    for (int mt = 0; mt < 4; mt++) {
        #pragma unroll
        for (int nt = 0; nt < 8; nt++) {
            int row = m0 + wm0 + mt * 16 + (lane >> 2);
            int col = n0 + wn0 + nt * 8 + ((lane & 3) << 1);
            #pragma unroll
            for (int hf = 0; hf < 2; hf++) {
                int r = row + hf * 8;
                float2 v = make_float2(acc[mt][nt][2*hf], acc[mt][nt][2*hf + 1]);
                if (mode == 0) {
                    *(float2*)&C[(size_t)r * DD + col] = v;
                } else {
                    int bI = r >> 11, l = r & (LL - 1);
                    int hh = col >> 6, hd = col & 63;
                    size_t off = ((size_t)((bI * HH + hh) * LL + l) << 6) + hd;
                    if (mode == 1) {
                        *(float2*)&C[off] = v;
                    } else {
                        uint32_t vh, vl;
                        split2(v.x, v.y, vh, vl);
                        *(uint32_t*)&Ch[off] = vh;
                        *(uint32_t*)&Cl[off] = vl;
                    }
                }
            }
        }
    }
}

// ---------------------------------------------------------------------------
// Per-head LayerNorm over HD=64, fp32 in -> bf16 hi/lo out, scale folded.
// ---------------------------------------------------------------------------
__global__ __launch_bounds__(256) void ln_head_split(const float* __restrict__ X,
                                                     const float* __restrict__ gamma,
                                                     const float* __restrict__ beta,
                                                     __nv_bfloat16* __restrict__ Xh,
                                                     __nv_bfloat16* __restrict__ Xl,
                                                     float scale)
{
    int row  = blockIdx.x * 8 + (threadIdx.x >> 5);
    int lane = threadIdx.x & 31;
    float2 v = *(const float2*)&X[(size_t)row * 64 + lane * 2];
    float s  = v.x + v.y;
    float sq = v.x * v.x + v.y * v.y;
    #pragma unroll
    for (int off = 16; off > 0; off >>= 1) {
        s  += __shfl_xor_sync(0xffffffffu, s,  off);
        sq += __shfl_xor_sync(0xffffffffu, sq, off);
    }
    float mean = s * (1.0f / 64.0f);
    float var  = sq * (1.0f / 64.0f) - mean * mean;
    float inv  = rsqrtf(var + 1e-5f);
    float g0 = gamma[lane * 2] * scale, g1 = gamma[lane * 2 + 1] * scale;
    float b0 = beta[lane * 2] * scale,  b1 = beta[lane * 2 + 1] * scale;
    v.x = (v.x - mean) * (inv * g0) + b0;
    v.y = (v.y - mean) * (inv * g1) + b1;
    uint32_t h, l;
    split2(v.x, v.y, h, l);
    *(uint32_t*)&Xh[(size_t)row * 64 + lane * 2] = h;
    *(uint32_t*)&Xl[(size_t)row * 64 + lane * 2] = l;
}

// ===========================================================================
// Tensor-core causal flash attention. 8 warps x 16 Q-rows, BK=128, bf16x3.
// Epilogue writes fp16 ctx (consumed by the fp16 out-projection).
// ===========================================================================
#define CS 0.18033688f   // 0.125 * log2(e)
#define FBUF 65536       // bytes per flash buffer

__global__ __launch_bounds__(256, 1) void flash_mma(
    const __nv_bfloat16* __restrict__ Qh, const __nv_bfloat16* __restrict__ Ql,
    const __nv_bfloat16* __restrict__ Kh, const __nv_bfloat16* __restrict__ Kl,
    const __nv_bfloat16* __restrict__ Vh, const __nv_bfloat16* __restrict__ Vl,
    __half* __restrict__ ctxf)
{
    extern __shared__ char fsm[];
    const uint32_t smb = smem_u32(fsm);
    const int tid  = threadIdx.x;
    const int lane = tid & 31;
    const int w    = tid >> 5;
    const int bh   = blockIdx.x;
    const int qt   = (gridDim.y - 1) - blockIdx.y;   // heavy CTAs first

    const __nv_bfloat16* Qhg = Qh + (size_t)bh * LL * HDD;
    const __nv_bfloat16* Qlg = Ql + (size_t)bh * LL * HDD;
    const __nv_bfloat16* Khg = Kh + (size_t)bh * LL * HDD;
    const __nv_bfloat16* Klg = Kl + (size_t)bh * LL * HDD;
    const __nv_bfloat16* Vhg = Vh + (size_t)bh * LL * HDD;
    const __nv_bfloat16* Vlg = Vl + (size_t)bh * LL * HDD;

    const int wq = qt * 128 + w * 16;

    uint32_t Qah[4][4], Qal[4][4];
    {
        int ra = wq + (lane >> 2);
        #pragma unroll
        for (int ks = 0; ks < 4; ks++) {
            int d0 = ks * 16 + (lane & 3) * 2;
            Qah[ks][0] = *(const uint32_t*)&Qhg[(size_t)ra * 64 + d0];
            Qah[ks][1] = *(const uint32_t*)&Qhg[(size_t)(ra + 8) * 64 + d0];
            Qah[ks][2] = *(const uint32_t*)&Qhg[(size_t)ra * 64 + d0 + 8];
            Qah[ks][3] = *(const uint32_t*)&Qhg[(size_t)(ra + 8) * 64 + d0 + 8];
            Qal[ks][0] = *(const uint32_t*)&Qlg[(size_t)ra * 64 + d0];
            Qal[ks][1] = *(const uint32_t*)&Qlg[(size_t)(ra + 8) * 64 + d0];
            Qal[ks][2] = *(const uint32_t*)&Qlg[(size_t)ra * 64 + d0 + 8];
            Qal[ks][3] = *(const uint32_t*)&Qlg[(size_t)(ra + 8) * 64 + d0 + 8];
        }
    }

    float o[8][4] = {};
    float l0 = 0.0f, l1 = 0.0f;

    const int nkt    = qt + 1;
    const int my_nkt = ((wq + 15) >> 7) + 1;

    auto prefetch = [&](int kt, int bufb) {
        #pragma unroll
        for (int j = 0; j < 16; j++) {
            const int tile = j >> 2;
            int c   = (j & 3) * 256 + tid;
            int row = c >> 3, ch = c & 7;
            const __nv_bfloat16* src =
                (tile == 0 ? Khg : tile == 1 ? Klg : tile == 2 ? Vhg : Vlg)
                + (size_t)(kt * 128 + row) * 64 + ch * 8;
            uint32_t dst = smb + bufb * FBUF + tile * 16384 + row * 128
                         + ((ch ^ (row & 7)) << 4);
            cp16(dst, src);
        }
    };

    prefetch(0, 0);
    CP_COMMIT();

    for (int kt = 0; kt < nkt; kt++) {
        const int buf = kt & 1;
        if (kt + 1 < nkt) prefetch(kt + 1, buf ^ 1);
        CP_COMMIT();
        CP_WAIT1();
        __syncthreads();

        if (kt < my_nkt) {
            const uint32_t bKh = smb + buf * FBUF;
            const uint32_t bKl = bKh + 16384;
            const uint32_t bVh = bKh + 32768;
            const uint32_t bVl = bKh + 49152;

            float s[16][4] = {};
            #pragma unroll
            for (int ks = 0; ks < 4; ks++) {
                #pragma unroll
                for (int ntp = 0; ntp < 8; ntp++) {
                    int mat  = lane >> 3;
                    int key  = ntp * 16 + (mat >> 1) * 8 + (lane & 7);
                    int ch   = 2 * ks + (mat & 1);
                    uint32_t off = key * 128 + (((ch ^ (key & 7))) << 4);
                    uint32_t kh[4], kl[4];
                    ldmx4(kh, bKh + off);
                    ldmx4(kl, bKl + off);
                    mma_bf16(s[2*ntp],   Qah[ks], kh);
                    mma_bf16(s[2*ntp],   Qah[ks], kl);
                    mma_bf16(s[2*ntp],   Qal[ks], kh);
                    mma_bf16(s[2*ntp+1], Qah[ks], kh + 2);
                    mma_bf16(s[2*ntp+1], Qah[ks], kl + 2);
                    mma_bf16(s[2*ntp+1], Qal[ks], kh + 2);
                }
            }

            if ((kt << 7) + 127 > wq) {
                int q0 = wq + (lane >> 2), q1 = q0 + 8;
                #pragma unroll
                for (int nt = 0; nt < 16; nt++) {
                    int key = (kt << 7) + nt * 8 + ((lane & 3) << 1);
                    if (key     > q0) s[nt][0] = -1e30f;
                    if (key + 1 > q0) s[nt][1] = -1e30f;
                    if (key     > q1) s[nt][2] = -1e30f;
                    if (key + 1 > q1) s[nt][3] = -1e30f;
                }
            }

            #pragma unroll
            for (int nt = 0; nt < 16; nt++) {
                float p0 = exp2p(s[nt][0]);
                float p1 = exp2p(s[nt][1]);
                float p2 = exp2p(s[nt][2]);
                float p3 = exp2p(s[nt][3]);
                s[nt][0] = p0; s[nt][1] = p1; s[nt][2] = p2; s[nt][3] = p3;
                l0 += p0 + p1;
                l1 += p2 + p3;
            }

            #pragma unroll
            for (int ks = 0; ks < 8; ks++) {
                uint32_t Ph[4], Pl[4];
                split2(s[2*ks][0],   s[2*ks][1],   Ph[0], Pl[0]);
                split2(s[2*ks][2],   s[2*ks][3],   Ph[1], Pl[1]);
                split2(s[2*ks+1][0], s[2*ks+1][1], Ph[2], Pl[2]);
                split2(s[2*ks+1][2], s[2*ks+1][3], Ph[3], Pl[3]);
                #pragma unroll
                for (int ntp = 0; ntp < 4; ntp++) {
                    int mat = lane >> 3;
                    int kk  = ks * 16 + (mat & 1) * 8 + (lane & 7);
                    int ch  = ntp * 2 + (mat >> 1);
                    uint32_t off = kk * 128 + (((ch ^ (kk & 7))) << 4);
                    uint32_t vh[4], vl[4];
                    ldmx4t(vh, bVh + off);
                    ldmx4t(vl, bVl + off);
                    mma_bf16(o[2*ntp],   Ph, vh);
                    mma_bf16(o[2*ntp],   Ph, vl);
                    mma_bf16(o[2*ntp],   Pl, vh);
                    mma_bf16(o[2*ntp+1], Ph, vh + 2);
                    mma_bf16(o[2*ntp+1], Ph, vl + 2);
                    mma_bf16(o[2*ntp+1], Pl, vh + 2);
                }
            }
        }
        __syncthreads();
    }

    l0 += __shfl_xor_sync(0xffffffffu, l0, 1);
    l0 += __shfl_xor_sync(0xffffffffu, l0, 2);
    l1 += __shfl_xor_sync(0xffffffffu, l1, 1);
    l1 += __shfl_xor_sync(0xffffffffu, l1, 2);

    // ---- epilogue: normalize, write fp16 ctx [b,l,d] ----
    const int b = bh >> 4, hdh = bh & 15;
    const int q0 = wq + (lane >> 2), q1 = q0 + 8;
    float inv0 = 1.0f / l0, inv1 = 1.0f / l1;
    #pragma unroll
    for (int nt = 0; nt < 8; nt++) {
        int d = nt * 8 + ((lane & 3) << 1);
        size_t o0 = (size_t)(b * LL + q0) * DD + hdh * 64 + d;
        size_t o1 = (size_t)(b * LL + q1) * DD + hdh * 64 + d;
        __half2 h0 = __floats2half2_rn(o[nt][0] * inv0, o[nt][1] * inv0);
        __half2 h1 = __floats2half2_rn(o[nt][2] * inv1, o[nt][3] * inv1);
        *(uint32_t*)&ctxf[o0] = *(uint32_t*)&h0;
        *(uint32_t*)&ctxf[o1] = *(uint32_t*)&h1;
    }
}

// ---------------------------------------------------------------------------
extern "C" void kernel_launch(void* const* d_in, const int* in_sizes, int n_in,
                              void* d_out, int out_size)
{
    const float* x      = (const float*)d_in[0];
    // d_in[1] = causal mask (tril) — causality applied analytically, unused
    const float* Wq     = (const float*)d_in[2];
    const float* Wk     = (const float*)d_in[3];
    const float* Wv     = (const float*)d_in[4];
    const float* Wo     = (const float*)d_in[5];
    const float* qgamma = (const float*)d_in[6];
    const float* qbeta  = (const float*)d_in[7];
    const float* kgamma = (const float*)d_in[8];
    const float* kbeta  = (const float*)d_in[9];
    float* out = (float*)d_out;

    float *dQ, *dK;
    __half *dxf, *dWq16, *dWk16, *dWv16, *dWo16, *dCf;
    __nv_bfloat16 *dQh, *dQl, *dKh, *dKl, *dVh, *dVl;
    cudaGetSymbolAddress((void**)&dQ,  g_Q);
    cudaGetSymbolAddress((void**)&dK,  g_K);
    cudaGetSymbolAddress((void**)&dxf, g_xf);
    cudaGetSymbolAddress((void**)&dCf, g_Cf);
    cudaGetSymbolAddress((void**)&dWq16, g_Wq16);
    cudaGetSymbolAddress((void**)&dWk16, g_Wk16);
    cudaGetSymbolAddress((void**)&dWv16, g_Wv16);
    cudaGetSymbolAddress((void**)&dWo16, g_Wo16);
    cudaGetSymbolAddress((void**)&dQh, g_Qh);   cudaGetSymbolAddress((void**)&dQl, g_Ql);
    cudaGetSymbolAddress((void**)&dKh, g_Kh);   cudaGetSymbolAddress((void**)&dKl, g_Kl);
    cudaGetSymbolAddress((void**)&dVh, g_Vh);   cudaGetSymbolAddress((void**)&dVl, g_Vl);

    const int gemm_smem  = 2 * GBUF;   // 64 KB
    const int flash_smem = 2 * FBUF;   // 128 KB
    cudaFuncSetAttribute(gemm_fp16,
                         cudaFuncAttributeMaxDynamicSharedMemorySize, gemm_smem);
    cudaFuncSetAttribute(flash_mma,
                         cudaFuncAttributeMaxDynamicSharedMemorySize, flash_smem);

    // fp16 operand conversion
    tohalf<<<NEL / 1024, 256>>>(x, dxf);
    tohalf_w4<<<4 * (DD * DD / 1024), 256>>>(Wq, Wk, Wv, Wo,
                                             dWq16, dWk16, dWv16, dWo16);

    dim3 gg(DD / 128, NTOK / 128);   // (8, 64)

    gemm_fp16<<<gg, 128, gemm_smem>>>(dxf, dWq16, dQ, nullptr, nullptr, 1);
    gemm_fp16<<<gg, 128, gemm_smem>>>(dxf, dWk16, dK, nullptr, nullptr, 1);
    gemm_fp16<<<gg, 128, gemm_smem>>>(dxf, dWv16, nullptr, dVh, dVl, 2);

    ln_head_split<<<(BB * HH * LL) / 8, 256>>>(dQ, qgamma, qbeta, dQh, dQl, CS);
    ln_head_split<<<(BB * HH * LL) / 8, 256>>>(dK, kgamma, kbeta, dKh, dKl, 1.0f);

    flash_mma<<<dim3(BB * HH, LL / 128), 256, flash_smem>>>(dQh, dQl, dKh, dKl,
                                                            dVh, dVl, dCf);

    gemm_fp16<<<gg, 128, gemm_smem>>>(dCf, dWo16, out, nullptr, nullptr, 0);
}

// round 14
// speedup vs baseline: 2.0088x; 1.1870x over previous
#include <cuda_runtime.h>
#include <cuda_bf16.h>
#include <cuda_fp16.h>
#include <math.h>
#include <stdint.h>

#define BB 4
#define LL 2048
#define DD 1024
#define HH 16
#define HDD 64
#define NTOK (BB*LL)            // 8192 rows
#define NEL  (BB*HH*LL*HDD)     // 8.4M elements

// Scratch (device globals — no allocations allowed)
__device__ float g_Q[NEL];      // fp32 head-major pre-LN
__device__ float g_K[NEL];
__device__ __align__(16) __half g_xf[NEL];          // x fp16
__device__ __align__(16) __half g_Wq16[DD*DD], g_Wk16[DD*DD];
__device__ __align__(16) __half g_Wv16[DD*DD], g_Wo16[DD*DD];
__device__ __align__(16) __half g_Cf[NEL];          // ctx fp16
__device__ __align__(16) __half g_Vf[NEL];          // V fp16 head-major
__device__ __align__(16) __nv_bfloat16 g_Qh[NEL], g_Ql[NEL];
__device__ __align__(16) __nv_bfloat16 g_Kh[NEL], g_Kl[NEL];

// ===========================================================================
// helpers
// ===========================================================================
__device__ __forceinline__ uint32_t smem_u32(const void* p) {
    uint32_t a;
    asm("{ .reg .u64 t; cvta.to.shared.u64 t, %1; cvt.u32.u64 %0, t; }"
        : "=r"(a) : "l"(p));
    return a;
}

__device__ __forceinline__ void mma_bf16(float* c, const uint32_t* a, const uint32_t* b) {
    asm volatile(
        "mma.sync.aligned.m16n8k16.row.col.f32.bf16.bf16.f32 "
        "{%0,%1,%2,%3}, {%4,%5,%6,%7}, {%8,%9}, {%0,%1,%2,%3};"
        : "+f"(c[0]), "+f"(c[1]), "+f"(c[2]), "+f"(c[3])
        : "r"(a[0]), "r"(a[1]), "r"(a[2]), "r"(a[3]), "r"(b[0]), "r"(b[1]));
}

__device__ __forceinline__ void mma_fp16(float* c, const uint32_t* a, const uint32_t* b) {
    asm volatile(
        "mma.sync.aligned.m16n8k16.row.col.f32.f16.f16.f32 "
        "{%0,%1,%2,%3}, {%4,%5,%6,%7}, {%8,%9}, {%0,%1,%2,%3};"
        : "+f"(c[0]), "+f"(c[1]), "+f"(c[2]), "+f"(c[3])
        : "r"(a[0]), "r"(a[1]), "r"(a[2]), "r"(a[3]), "r"(b[0]), "r"(b[1]));
}

__device__ __forceinline__ void ldmx4(uint32_t* r, uint32_t addr) {
    asm volatile("ldmatrix.sync.aligned.m8n8.x4.shared.b16 {%0,%1,%2,%3}, [%4];"
                 : "=r"(r[0]), "=r"(r[1]), "=r"(r[2]), "=r"(r[3]) : "r"(addr));
}
__device__ __forceinline__ void ldmx4t(uint32_t* r, uint32_t addr) {
    asm volatile("ldmatrix.sync.aligned.m8n8.x4.trans.shared.b16 {%0,%1,%2,%3}, [%4];"
                 : "=r"(r[0]), "=r"(r[1]), "=r"(r[2]), "=r"(r[3]) : "r"(addr));
}

__device__ __forceinline__ void cp16(uint32_t dst, const void* src) {
    asm volatile("cp.async.cg.shared.global [%0], [%1], 16;" :: "r"(dst), "l"(src));
}
#define CP_COMMIT() asm volatile("cp.async.commit_group;" ::: "memory")
#define CP_WAIT1()  asm volatile("cp.async.wait_group 1;" ::: "memory")

// split two floats into packed bf16 hi + bf16 lo (residual)
__device__ __forceinline__ void split2(float a, float b, uint32_t& h, uint32_t& l) {
    __nv_bfloat16 ha = __float2bfloat16_rn(a);
    __nv_bfloat16 hb = __float2bfloat16_rn(b);
    float ra = a - __bfloat162float(ha);
    float rb = b - __bfloat162float(hb);
    __nv_bfloat162 hv; hv.x = ha; hv.y = hb;
    __nv_bfloat162 lv = __floats2bfloat162_rn(ra, rb);
    h = *(uint32_t*)&hv;
    l = *(uint32_t*)&lv;
}

__device__ __forceinline__ uint32_t h2pack(float a, float b) {
    __half2 h = __floats2half2_rn(a, b);
    return *(uint32_t*)&h;
}

// fast 2^t on FMA/ALU pipes (no MUFU). clamped at -100; t <= ~12 here.
__device__ __forceinline__ float exp2p(float t) {
    t = fmaxf(t, -100.0f);
    float z = t + 12582912.0f;
    float f = t - (z - 12582912.0f);
    float p =             1.3333558e-3f;
    p = fmaf(p, f, 9.6181291e-3f);
    p = fmaf(p, f, 5.5504109e-2f);
    p = fmaf(p, f, 2.4022651e-1f);
    p = fmaf(p, f, 6.9314718e-1f);
    p = fmaf(p, f, 1.0f);
    return __int_as_float(__float_as_int(p) + (__float_as_int(z) << 23));
}

// ---------------------------------------------------------------------------
// fp32 -> fp16 converters
// ---------------------------------------------------------------------------
__global__ __launch_bounds__(256) void tohalf(const float* __restrict__ X,
                                              __half* __restrict__ Y)
{
    int i = blockIdx.x * 256 + threadIdx.x;
    float4 v = ((const float4*)X)[i];
    ((uint2*)Y)[i] = make_uint2(h2pack(v.x, v.y), h2pack(v.z, v.w));
}

__global__ __launch_bounds__(256) void tohalf_w4(const float* __restrict__ W0,
                                                 const float* __restrict__ W1,
                                                 const float* __restrict__ W2,
                                                 const float* __restrict__ W3,
                                                 __half* __restrict__ Y0,
                                                 __half* __restrict__ Y1,
                                                 __half* __restrict__ Y2,
                                                 __half* __restrict__ Y3)
{
    int which = blockIdx.x >> 10;
    int i = (blockIdx.x & 1023) * 256 + threadIdx.x;
    const float* W = which == 0 ? W0 : which == 1 ? W1 : which == 2 ? W2 : W3;
    __half* Y = which == 0 ? Y0 : which == 1 ? Y1 : which == 2 ? Y2 : Y3;
    float4 v = ((const float4*)W)[i];
    ((uint2*)Y)[i] = make_uint2(h2pack(v.x, v.y), h2pack(v.z, v.w));
}

// ===========================================================================
// fp16 single-mma GEMM: C[M,1024] = A @ B^T
// CTA 128x128, BK=64, 4 warps of 64x64 (128 threads), 2 CTA/SM.
// mode 0: fp32 row-major; 1: fp32 head-major; 2: fp16 head-major (V).
// ===========================================================================
#define GBUF 32768

__global__ __launch_bounds__(128, 2) void gemm_fp16(const __half* __restrict__ A,
                                                    const __half* __restrict__ B,
                                                    float* __restrict__ C,
                                                    __half* __restrict__ C16,
                                                    int mode)
{
    extern __shared__ char gsm[];
    const uint32_t smb = smem_u32(gsm);
    const int tid  = threadIdx.x;
    const int lane = tid & 31;
    const int wid  = tid >> 5;
    const int wm0  = (wid & 1) * 64;
    const int wn0  = (wid >> 1) * 64;
    const int m0   = blockIdx.y * 128;
    const int n0   = blockIdx.x * 128;
    const int mat  = lane >> 3;

    float acc[4][8][4] = {};

    auto prefetch = [&](int kc, int b) {
        #pragma unroll
        for (int j = 0; j < 16; j++) {
            const int tile = j >> 3;
            int c   = (j & 7) * 128 + tid;
            int row = c >> 3, ch = c & 7;
            int grow = (tile == 0 ? m0 : n0) + row;
            const __half* src = (tile == 0 ? A : B) + (size_t)grow * DD + kc * 64 + ch * 8;
            uint32_t dst = smb + b * GBUF + tile * 16384 + row * 128
                         + ((ch ^ (row & 7)) << 4);
            cp16(dst, src);
        }
    };

    prefetch(0, 0);
    CP_COMMIT();

    for (int kc = 0; kc < 16; kc++) {
        const int buf = kc & 1;
        if (kc + 1 < 16) prefetch(kc + 1, buf ^ 1);
        CP_COMMIT();
        CP_WAIT1();
        __syncthreads();

        const uint32_t bA = smb + buf * GBUF;
        const uint32_t bB = bA + 16384;

        #pragma unroll
        for (int ks = 0; ks < 4; ks++) {
            uint32_t aF[4][4];
            #pragma unroll
            for (int mt = 0; mt < 4; mt++) {
                int r  = wm0 + mt * 16 + ((mat & 1) << 3) + (lane & 7);
                int ch = 2 * ks + (mat >> 1);
                uint32_t off = r * 128 + ((ch ^ (r & 7)) << 4);
                ldmx4(aF[mt], bA + off);
            }
            uint32_t bF[4][4];
            #pragma unroll
            for (int np = 0; np < 4; np++) {
                int rn = wn0 + np * 16 + ((mat >> 1) << 3) + (lane & 7);
                int ch = 2 * ks + (mat & 1);
                uint32_t off = rn * 128 + ((ch ^ (rn & 7)) << 4);
                ldmx4(bF[np], bB + off);
            }
            #pragma unroll
            for (int mt = 0; mt < 4; mt++)
                #pragma unroll
                for (int np = 0; np < 4; np++) {
                    mma_fp16(acc[mt][2*np],   aF[mt], bF[np]);
                    mma_fp16(acc[mt][2*np+1], aF[mt], bF[np] + 2);
                }
        }
        __syncthreads();
    }

    #pragma unroll
    for (int mt = 0; mt < 4; mt++) {
        #pragma unroll
        for (int nt = 0; nt < 8; nt++) {
            int row = m0 + wm0 + mt * 16 + (lane >> 2);
            int col = n0 + wn0 + nt * 8 + ((lane & 3) << 1);
            #pragma unroll
            for (int hf = 0; hf < 2; hf++) {
                int r = row + hf * 8;
                float2 v = make_float2(acc[mt][nt][2*hf], acc[mt][nt][2*hf + 1]);
                if (mode == 0) {
                    *(float2*)&C[(size_t)r * DD + col] = v;
                } else {
                    int bI = r >> 11, l = r & (LL - 1);
                    int hh = col >> 6, hd = col & 63;
                    size_t off = ((size_t)((bI * HH + hh) * LL + l) << 6) + hd;
                    if (mode == 1) {
                        *(float2*)&C[off] = v;
                    } else {
                        *(uint32_t*)&C16[off] = h2pack(v.x, v.y);
                    }
                }
            }
        }
    }
}

// ---------------------------------------------------------------------------
// Per-head LayerNorm over HD=64, fp32 in -> bf16 hi/lo out, scale folded.
// ---------------------------------------------------------------------------
__global__ __launch_bounds__(256) void ln_head_split(const float* __restrict__ X,
                                                     const float* __restrict__ gamma,
                                                     const float* __restrict__ beta,
                                                     __nv_bfloat16* __restrict__ Xh,
                                                     __nv_bfloat16* __restrict__ Xl,
                                                     float scale)
{
    int row  = blockIdx.x * 8 + (threadIdx.x >> 5);
    int lane = threadIdx.x & 31;
    float2 v = *(const float2*)&X[(size_t)row * 64 + lane * 2];
    float s  = v.x + v.y;
    float sq = v.x * v.x + v.y * v.y;
    #pragma unroll
    for (int off = 16; off > 0; off >>= 1) {
        s  += __shfl_xor_sync(0xffffffffu, s,  off);
        sq += __shfl_xor_sync(0xffffffffu, sq, off);
    }
    float mean = s * (1.0f / 64.0f);
    float var  = sq * (1.0f / 64.0f) - mean * mean;
    float inv  = rsqrtf(var + 1e-5f);
    float g0 = gamma[lane * 2] * scale, g1 = gamma[lane * 2 + 1] * scale;
    float b0 = beta[lane * 2] * scale,  b1 = beta[lane * 2 + 1] * scale;
    v.x = (v.x - mean) * (inv * g0) + b0;
    v.y = (v.y - mean) * (inv * g1) + b1;
    uint32_t h, l;
    split2(v.x, v.y, h, l);
    *(uint32_t*)&Xh[(size_t)row * 64 + lane * 2] = h;
    *(uint32_t*)&Xl[(size_t)row * 64 + lane * 2] = l;
}

// ===========================================================================
// Tensor-core causal flash attention. 8 warps x 16 Q-rows, BK=128.
// QK^T: bf16x3 (score precision). PV: fp16 single-mma (P in [0,1], V fp16).
// Buffers: Kh,Kl (bf16) + Vf (fp16) = 48KB; x2 = 96KB smem.
// ===========================================================================
#define CS 0.18033688f   // 0.125 * log2(e)
#define FBUF 49152       // bytes per flash buffer

__global__ __launch_bounds__(256, 1) void flash_mma(
    const __nv_bfloat16* __restrict__ Qh, const __nv_bfloat16* __restrict__ Ql,
    const __nv_bfloat16* __restrict__ Kh, const __nv_bfloat16* __restrict__ Kl,
    const __half* __restrict__ Vf,
    __half* __restrict__ ctxf)
{
    extern __shared__ char fsm[];
    const uint32_t smb = smem_u32(fsm);
    const int tid  = threadIdx.x;
    const int lane = tid & 31;
    const int w    = tid >> 5;
    const int bh   = blockIdx.x;
    const int qt   = (gridDim.y - 1) - blockIdx.y;   // heavy CTAs first

    const __nv_bfloat16* Qhg = Qh + (size_t)bh * LL * HDD;
    const __nv_bfloat16* Qlg = Ql + (size_t)bh * LL * HDD;
    const __nv_bfloat16* Khg = Kh + (size_t)bh * LL * HDD;
    const __nv_bfloat16* Klg = Kl + (size_t)bh * LL * HDD;
    const __half*        Vfg = Vf + (size_t)bh * LL * HDD;

    const int wq = qt * 128 + w * 16;

    uint32_t Qah[4][4], Qal[4][4];
    {
        int ra = wq + (lane >> 2);
        #pragma unroll
        for (int ks = 0; ks < 4; ks++) {
            int d0 = ks * 16 + (lane & 3) * 2;
            Qah[ks][0] = *(const uint32_t*)&Qhg[(size_t)ra * 64 + d0];
            Qah[ks][1] = *(const uint32_t*)&Qhg[(size_t)(ra + 8) * 64 + d0];
            Qah[ks][2] = *(const uint32_t*)&Qhg[(size_t)ra * 64 + d0 + 8];
            Qah[ks][3] = *(const uint32_t*)&Qhg[(size_t)(ra + 8) * 64 + d0 + 8];
            Qal[ks][0] = *(const uint32_t*)&Qlg[(size_t)ra * 64 + d0];
            Qal[ks][1] = *(const uint32_t*)&Qlg[(size_t)(ra + 8) * 64 + d0];
            Qal[ks][2] = *(const uint32_t*)&Qlg[(size_t)ra * 64 + d0 + 8];
            Qal[ks][3] = *(const uint32_t*)&Qlg[(size_t)(ra + 8) * 64 + d0 + 8];
        }
    }

    float o[8][4] = {};
    float l0 = 0.0f, l1 = 0.0f;

    const int nkt    = qt + 1;
    const int my_nkt = ((wq + 15) >> 7) + 1;

    // prefetch: 3 tiles (Kh,Kl,Vf) x 128 rows x 8 chunks = 3072 chunks / 256
    auto prefetch = [&](int kt, int bufb) {
        #pragma unroll
        for (int j = 0; j < 12; j++) {
            const int tile = j >> 2;
            int c   = (j & 3) * 256 + tid;
            int row = c >> 3, ch = c & 7;
            const void* src;
            if (tile == 0)      src = Khg + (size_t)(kt * 128 + row) * 64 + ch * 8;
            else if (tile == 1) src = Klg + (size_t)(kt * 128 + row) * 64 + ch * 8;
            else                src = Vfg + (size_t)(kt * 128 + row) * 64 + ch * 8;
            uint32_t dst = smb + bufb * FBUF + tile * 16384 + row * 128
                         + ((ch ^ (row & 7)) << 4);
            cp16(dst, src);
        }
    };

    prefetch(0, 0);
    CP_COMMIT();

    for (int kt = 0; kt < nkt; kt++) {
        const int buf = kt & 1;
        if (kt + 1 < nkt) prefetch(kt + 1, buf ^ 1);
        CP_COMMIT();
        CP_WAIT1();
        __syncthreads();

        if (kt < my_nkt) {
            const uint32_t bKh = smb + buf * FBUF;
            const uint32_t bKl = bKh + 16384;
            const uint32_t bVf = bKh + 32768;

            // ---- S = Q K^T (bf16x3), log2 scale ----
            float s[16][4] = {};
            #pragma unroll
            for (int ks = 0; ks < 4; ks++) {
                #pragma unroll
                for (int ntp = 0; ntp < 8; ntp++) {
                    int mat  = lane >> 3;
                    int key  = ntp * 16 + (mat >> 1) * 8 + (lane & 7);
                    int ch   = 2 * ks + (mat & 1);
                    uint32_t off = key * 128 + (((ch ^ (key & 7))) << 4);
                    uint32_t kh[4], kl[4];
                    ldmx4(kh, bKh + off);
                    ldmx4(kl, bKl + off);
                    mma_bf16(s[2*ntp],   Qah[ks], kh);
                    mma_bf16(s[2*ntp],   Qah[ks], kl);
                    mma_bf16(s[2*ntp],   Qal[ks], kh);
                    mma_bf16(s[2*ntp+1], Qah[ks], kh + 2);
                    mma_bf16(s[2*ntp+1], Qah[ks], kl + 2);
                    mma_bf16(s[2*ntp+1], Qal[ks], kh + 2);
                }
            }

            // ---- causal mask ----
            if ((kt << 7) + 127 > wq) {
                int q0 = wq + (lane >> 2), q1 = q0 + 8;
                #pragma unroll
                for (int nt = 0; nt < 16; nt++) {
                    int key = (kt << 7) + nt * 8 + ((lane & 3) << 1);
                    if (key     > q0) s[nt][0] = -1e30f;
                    if (key + 1 > q0) s[nt][1] = -1e30f;
                    if (key     > q1) s[nt][2] = -1e30f;
                    if (key + 1 > q1) s[nt][3] = -1e30f;
                }
            }

            // ---- p = exp2(s), lane-local sums ----
            #pragma unroll
            for (int nt = 0; nt < 16; nt++) {
                float p0 = exp2p(s[nt][0]);
                float p1 = exp2p(s[nt][1]);
                float p2 = exp2p(s[nt][2]);
                float p3 = exp2p(s[nt][3]);
                s[nt][0] = p0; s[nt][1] = p1; s[nt][2] = p2; s[nt][3] = p3;
                l0 += p0 + p1;
                l1 += p2 + p3;
            }

            // ---- O += P V (fp16 single-mma) ----
            #pragma unroll
            for (int ks = 0; ks < 8; ks++) {
                uint32_t Pf[4];
                Pf[0] = h2pack(s[2*ks][0],   s[2*ks][1]);
                Pf[1] = h2pack(s[2*ks][2],   s[2*ks][3]);
                Pf[2] = h2pack(s[2*ks+1][0], s[2*ks+1][1]);
                Pf[3] = h2pack(s[2*ks+1][2], s[2*ks+1][3]);
                #pragma unroll
                for (int ntp = 0; ntp < 4; ntp++) {
                    int mat = lane >> 3;
                    int kk  = ks * 16 + (mat & 1) * 8 + (lane & 7);
                    int ch  = ntp * 2 + (mat >> 1);
                    uint32_t off = kk * 128 + (((ch ^ (kk & 7))) << 4);
                    uint32_t vf[4];
                    ldmx4t(vf, bVf + off);
                    mma_fp16(o[2*ntp],   Pf, vf);
                    mma_fp16(o[2*ntp+1], Pf, vf + 2);
                }
            }
        }
        __syncthreads();
    }

    l0 += __shfl_xor_sync(0xffffffffu, l0, 1);
    l0 += __shfl_xor_sync(0xffffffffu, l0, 2);
    l1 += __shfl_xor_sync(0xffffffffu, l1, 1);
    l1 += __shfl_xor_sync(0xffffffffu, l1, 2);

    // ---- epilogue: normalize, write fp16 ctx [b,l,d] ----
    const int b = bh >> 4, hdh = bh & 15;
    const int q0 = wq + (lane >> 2), q1 = q0 + 8;
    float inv0 = 1.0f / l0, inv1 = 1.0f / l1;
    #pragma unroll
    for (int nt = 0; nt < 8; nt++) {
        int d = nt * 8 + ((lane & 3) << 1);
        size_t o0 = (size_t)(b * LL + q0) * DD + hdh * 64 + d;
        size_t o1 = (size_t)(b * LL + q1) * DD + hdh * 64 + d;
        *(uint32_t*)&ctxf[o0] = h2pack(o[nt][0] * inv0, o[nt][1] * inv0);
        *(uint32_t*)&ctxf[o1] = h2pack(o[nt][2] * inv1, o[nt][3] * inv1);
    }
}

// ---------------------------------------------------------------------------
extern "C" void kernel_launch(void* const* d_in, const int* in_sizes, int n_in,
                              void* d_out, int out_size)
{
    const float* x      = (const float*)d_in[0];
    // d_in[1] = causal mask (tril) — causality applied analytically, unused
    const float* Wq     = (const float*)d_in[2];
    const float* Wk     = (const float*)d_in[3];
    const float* Wv     = (const float*)d_in[4];
    const float* Wo     = (const float*)d_in[5];
    const float* qgamma = (const float*)d_in[6];
    const float* qbeta  = (const float*)d_in[7];
    const float* kgamma = (const float*)d_in[8];
    const float* kbeta  = (const float*)d_in[9];
    float* out = (float*)d_out;

    float *dQ, *dK;
    __half *dxf, *dWq16, *dWk16, *dWv16, *dWo16, *dCf, *dVf;
    __nv_bfloat16 *dQh, *dQl, *dKh, *dKl;
    cudaGetSymbolAddress((void**)&dQ,  g_Q);
    cudaGetSymbolAddress((void**)&dK,  g_K);
    cudaGetSymbolAddress((void**)&dxf, g_xf);
    cudaGetSymbolAddress((void**)&dCf, g_Cf);
    cudaGetSymbolAddress((void**)&dVf, g_Vf);
    cudaGetSymbolAddress((void**)&dWq16, g_Wq16);
    cudaGetSymbolAddress((void**)&dWk16, g_Wk16);
    cudaGetSymbolAddress((void**)&dWv16, g_Wv16);
    cudaGetSymbolAddress((void**)&dWo16, g_Wo16);
    cudaGetSymbolAddress((void**)&dQh, g_Qh);   cudaGetSymbolAddress((void**)&dQl, g_Ql);
    cudaGetSymbolAddress((void**)&dKh, g_Kh);   cudaGetSymbolAddress((void**)&dKl, g_Kl);

    const int gemm_smem  = 2 * GBUF;   // 64 KB
    const int flash_smem = 2 * FBUF;   // 96 KB
    cudaFuncSetAttribute(gemm_fp16,
                         cudaFuncAttributeMaxDynamicSharedMemorySize, gemm_smem);
    cudaFuncSetAttribute(flash_mma,
                         cudaFuncAttributeMaxDynamicSharedMemorySize, flash_smem);

    // fp16 operand conversion
    tohalf<<<NEL / 1024, 256>>>(x, dxf);
    tohalf_w4<<<4 * (DD * DD / 1024), 256>>>(Wq, Wk, Wv, Wo,
                                             dWq16, dWk16, dWv16, dWo16);

    dim3 gg(DD / 128, NTOK / 128);   // (8, 64)

    gemm_fp16<<<gg, 128, gemm_smem>>>(dxf, dWq16, dQ, nullptr, 1);
    gemm_fp16<<<gg, 128, gemm_smem>>>(dxf, dWk16, dK, nullptr, 1);
    gemm_fp16<<<gg, 128, gemm_smem>>>(dxf, dWv16, nullptr, dVf, 2);

    ln_head_split<<<(BB * HH * LL) / 8, 256>>>(dQ, qgamma, qbeta, dQh, dQl, CS);
    ln_head_split<<<(BB * HH * LL) / 8, 256>>>(dK, kgamma, kbeta, dKh, dKl, 1.0f);

    flash_mma<<<dim3(BB * HH, LL / 128), 256, flash_smem>>>(dQh, dQl, dKh, dKl,
                                                            dVf, dCf);

    gemm_fp16<<<gg, 128, gemm_smem>>>(dCf, dWo16, out, nullptr, 0);
}

// round 15
// speedup vs baseline: 2.3867x; 1.1881x over previous
#include <cuda_runtime.h>
#include <cuda_fp16.h>
#include <math.h>
#include <stdint.h>

#define BB 4
#define LL 2048
#define DD 1024
#define HH 16
#define HDD 64
#define NTOK (BB*LL)            // 8192 rows
#define NEL  (BB*HH*LL*HDD)     // 8.4M elements

// Scratch (device globals — no allocations allowed)
__device__ float g_Q[NEL];      // fp32 head-major pre-LN
__device__ float g_K[NEL];
__device__ __align__(16) __half g_xf[NEL];          // x fp16
__device__ __align__(16) __half g_Wq16[DD*DD], g_Wk16[DD*DD];
__device__ __align__(16) __half g_Wv16[DD*DD], g_Wo16[DD*DD];
__device__ __align__(16) __half g_Cf[NEL];          // ctx fp16
__device__ __align__(16) __half g_Vf[NEL];          // V fp16 head-major
__device__ __align__(16) __half g_Qf[NEL];          // Q fp16 post-LN (CS folded)
__device__ __align__(16) __half g_Kf[NEL];          // K fp16 post-LN

// ===========================================================================
// helpers
// ===========================================================================
__device__ __forceinline__ uint32_t smem_u32(const void* p) {
    uint32_t a;
    asm("{ .reg .u64 t; cvta.to.shared.u64 t, %1; cvt.u32.u64 %0, t; }"
        : "=r"(a) : "l"(p));
    return a;
}

__device__ __forceinline__ void mma_fp16(float* c, const uint32_t* a, const uint32_t* b) {
    asm volatile(
        "mma.sync.aligned.m16n8k16.row.col.f32.f16.f16.f32 "
        "{%0,%1,%2,%3}, {%4,%5,%6,%7}, {%8,%9}, {%0,%1,%2,%3};"
        : "+f"(c[0]), "+f"(c[1]), "+f"(c[2]), "+f"(c[3])
        : "r"(a[0]), "r"(a[1]), "r"(a[2]), "r"(a[3]), "r"(b[0]), "r"(b[1]));
}

__device__ __forceinline__ void ldmx4(uint32_t* r, uint32_t addr) {
    asm volatile("ldmatrix.sync.aligned.m8n8.x4.shared.b16 {%0,%1,%2,%3}, [%4];"
                 : "=r"(r[0]), "=r"(r[1]), "=r"(r[2]), "=r"(r[3]) : "r"(addr));
}
__device__ __forceinline__ void ldmx4t(uint32_t* r, uint32_t addr) {
    asm volatile("ldmatrix.sync.aligned.m8n8.x4.trans.shared.b16 {%0,%1,%2,%3}, [%4];"
                 : "=r"(r[0]), "=r"(r[1]), "=r"(r[2]), "=r"(r[3]) : "r"(addr));
}

__device__ __forceinline__ void cp16(uint32_t dst, const void* src) {
    asm volatile("cp.async.cg.shared.global [%0], [%1], 16;" :: "r"(dst), "l"(src));
}
#define CP_COMMIT() asm volatile("cp.async.commit_group;" ::: "memory")
#define CP_WAIT1()  asm volatile("cp.async.wait_group 1;" ::: "memory")

__device__ __forceinline__ uint32_t h2pack(float a, float b) {
    __half2 h = __floats2half2_rn(a, b);
    return *(uint32_t*)&h;
}

// fast 2^t on FMA/ALU pipes (no MUFU). clamped at -100; t <= ~12 here.
__device__ __forceinline__ float exp2p(float t) {
    t = fmaxf(t, -100.0f);
    float z = t + 12582912.0f;
    float f = t - (z - 12582912.0f);
    float p =             1.3333558e-3f;
    p = fmaf(p, f, 9.6181291e-3f);
    p = fmaf(p, f, 5.5504109e-2f);
    p = fmaf(p, f, 2.4022651e-1f);
    p = fmaf(p, f, 6.9314718e-1f);
    p = fmaf(p, f, 1.0f);
    return __int_as_float(__float_as_int(p) + (__float_as_int(z) << 23));
}

// ---------------------------------------------------------------------------
// fp32 -> fp16 converters
// ---------------------------------------------------------------------------
__global__ __launch_bounds__(256) void tohalf(const float* __restrict__ X,
                                              __half* __restrict__ Y)
{
    int i = blockIdx.x * 256 + threadIdx.x;
    float4 v = ((const float4*)X)[i];
    ((uint2*)Y)[i] = make_uint2(h2pack(v.x, v.y), h2pack(v.z, v.w));
}

__global__ __launch_bounds__(256) void tohalf_w4(const float* __restrict__ W0,
                                                 const float* __restrict__ W1,
                                                 const float* __restrict__ W2,
                                                 const float* __restrict__ W3,
                                                 __half* __restrict__ Y0,
                                                 __half* __restrict__ Y1,
                                                 __half* __restrict__ Y2,
                                                 __half* __restrict__ Y3)
{
    int which = blockIdx.x >> 10;
    int i = (blockIdx.x & 1023) * 256 + threadIdx.x;
    const float* W = which == 0 ? W0 : which == 1 ? W1 : which == 2 ? W2 : W3;
    __half* Y = which == 0 ? Y0 : which == 1 ? Y1 : which == 2 ? Y2 : Y3;
    float4 v = ((const float4*)W)[i];
    ((uint2*)Y)[i] = make_uint2(h2pack(v.x, v.y), h2pack(v.z, v.w));
}

// ===========================================================================
// fp16 single-mma GEMM: C[M,1024] = A @ B^T
// CTA 128x128, BK=64, 4 warps of 64x64 (128 threads), 2 CTA/SM.
// mode 0: fp32 row-major; 1: fp32 head-major; 2: fp16 head-major (V).
// ===========================================================================
#define GBUF 32768

__global__ __launch_bounds__(128, 2) void gemm_fp16(const __half* __restrict__ A,
                                                    const __half* __restrict__ B,
                                                    float* __restrict__ C,
                                                    __half* __restrict__ C16,
                                                    int mode)
{
    extern __shared__ char gsm[];
    const uint32_t smb = smem_u32(gsm);
    const int tid  = threadIdx.x;
    const int lane = tid & 31;
    const int wid  = tid >> 5;
    const int wm0  = (wid & 1) * 64;
    const int wn0  = (wid >> 1) * 64;
    const int m0   = blockIdx.y * 128;
    const int n0   = blockIdx.x * 128;
    const int mat  = lane >> 3;

    float acc[4][8][4] = {};

    auto prefetch = [&](int kc, int b) {
        #pragma unroll
        for (int j = 0; j < 16; j++) {
            const int tile = j >> 3;
            int c   = (j & 7) * 128 + tid;
            int row = c >> 3, ch = c & 7;
            int grow = (tile == 0 ? m0 : n0) + row;
            const __half* src = (tile == 0 ? A : B) + (size_t)grow * DD + kc * 64 + ch * 8;
            uint32_t dst = smb + b * GBUF + tile * 16384 + row * 128
                         + ((ch ^ (row & 7)) << 4);
            cp16(dst, src);
        }
    };

    prefetch(0, 0);
    CP_COMMIT();

    for (int kc = 0; kc < 16; kc++) {
        const int buf = kc & 1;
        if (kc + 1 < 16) prefetch(kc + 1, buf ^ 1);
        CP_COMMIT();
        CP_WAIT1();
        __syncthreads();

        const uint32_t bA = smb + buf * GBUF;
        const uint32_t bB = bA + 16384;

        #pragma unroll
        for (int ks = 0; ks < 4; ks++) {
            uint32_t aF[4][4];
            #pragma unroll
            for (int mt = 0; mt < 4; mt++) {
                int r  = wm0 + mt * 16 + ((mat & 1) << 3) + (lane & 7);
                int ch = 2 * ks + (mat >> 1);
                uint32_t off = r * 128 + ((ch ^ (r & 7)) << 4);
                ldmx4(aF[mt], bA + off);
            }
            uint32_t bF[4][4];
            #pragma unroll
            for (int np = 0; np < 4; np++) {
                int rn = wn0 + np * 16 + ((mat >> 1) << 3) + (lane & 7);
                int ch = 2 * ks + (mat & 1);
                uint32_t off = rn * 128 + ((ch ^ (rn & 7)) << 4);
                ldmx4(bF[np], bB + off);
            }
            #pragma unroll
            for (int mt = 0; mt < 4; mt++)
                #pragma unroll
                for (int np = 0; np < 4; np++) {
                    mma_fp16(acc[mt][2*np],   aF[mt], bF[np]);
                    mma_fp16(acc[mt][2*np+1], aF[mt], bF[np] + 2);
                }
        }
        __syncthreads();
    }

    #pragma unroll
    for (int mt = 0; mt < 4; mt++) {
        #pragma unroll
        for (int nt = 0; nt < 8; nt++) {
            int row = m0 + wm0 + mt * 16 + (lane >> 2);
            int col = n0 + wn0 + nt * 8 + ((lane & 3) << 1);
            #pragma unroll
            for (int hf = 0; hf < 2; hf++) {
                int r = row + hf * 8;
                float2 v = make_float2(acc[mt][nt][2*hf], acc[mt][nt][2*hf + 1]);
                if (mode == 0) {
                    *(float2*)&C[(size_t)r * DD + col] = v;
                } else {
                    int bI = r >> 11, l = r & (LL - 1);
                    int hh = col >> 6, hd = col & 63;
                    size_t off = ((size_t)((bI * HH + hh) * LL + l) << 6) + hd;
                    if (mode == 1) {
                        *(float2*)&C[off] = v;
                    } else {
                        *(uint32_t*)&C16[off] = h2pack(v.x, v.y);
                    }
                }
            }
        }
    }
}

// ---------------------------------------------------------------------------
// Per-head LayerNorm over HD=64, fp32 in -> fp16 out, scale folded.
// ---------------------------------------------------------------------------
__global__ __launch_bounds__(256) void ln_head_f16(const float* __restrict__ X,
                                                   const float* __restrict__ gamma,
                                                   const float* __restrict__ beta,
                                                   __half* __restrict__ Xf,
                                                   float scale)
{
    int row  = blockIdx.x * 8 + (threadIdx.x >> 5);
    int lane = threadIdx.x & 31;
    float2 v = *(const float2*)&X[(size_t)row * 64 + lane * 2];
    float s  = v.x + v.y;
    float sq = v.x * v.x + v.y * v.y;
    #pragma unroll
    for (int off = 16; off > 0; off >>= 1) {
        s  += __shfl_xor_sync(0xffffffffu, s,  off);
        sq += __shfl_xor_sync(0xffffffffu, sq, off);
    }
    float mean = s * (1.0f / 64.0f);
    float var  = sq * (1.0f / 64.0f) - mean * mean;
    float inv  = rsqrtf(var + 1e-5f);
    float g0 = gamma[lane * 2] * scale, g1 = gamma[lane * 2 + 1] * scale;
    float b0 = beta[lane * 2] * scale,  b1 = beta[lane * 2 + 1] * scale;
    v.x = (v.x - mean) * (inv * g0) + b0;
    v.y = (v.y - mean) * (inv * g1) + b1;
    *(uint32_t*)&Xf[(size_t)row * 64 + lane * 2] = h2pack(v.x, v.y);
}

// ===========================================================================
// Tensor-core causal flash attention, ALL fp16 single-mma.
// 8 warps x 16 Q-rows, BK=128. Buffers {Kf,Vf} = 32KB; x2 = 64KB smem.
// Per key-tile per warp: QK 64 mma + PV 64 mma (was 192+64 with bf16x3 QK).
// ===========================================================================
#define CS 0.18033688f   // 0.125 * log2(e)
#define FBUF 32768       // bytes per flash buffer

__global__ __launch_bounds__(256, 1) void flash_mma(
    const __half* __restrict__ Qf, const __half* __restrict__ Kf,
    const __half* __restrict__ Vf,
    __half* __restrict__ ctxf)
{
    extern __shared__ char fsm[];
    const uint32_t smb = smem_u32(fsm);
    const int tid  = threadIdx.x;
    const int lane = tid & 31;
    const int w    = tid >> 5;
    const int bh   = blockIdx.x;
    const int qt   = (gridDim.y - 1) - blockIdx.y;   // heavy CTAs first

    const __half* Qfg = Qf + (size_t)bh * LL * HDD;
    const __half* Kfg = Kf + (size_t)bh * LL * HDD;
    const __half* Vfg = Vf + (size_t)bh * LL * HDD;

    const int wq = qt * 128 + w * 16;

    // ---- Q fragments (fp16, CS pre-folded) ----
    uint32_t Qa[4][4];
    {
        int ra = wq + (lane >> 2);
        #pragma unroll
        for (int ks = 0; ks < 4; ks++) {
            int d0 = ks * 16 + (lane & 3) * 2;
            Qa[ks][0] = *(const uint32_t*)&Qfg[(size_t)ra * 64 + d0];
            Qa[ks][1] = *(const uint32_t*)&Qfg[(size_t)(ra + 8) * 64 + d0];
            Qa[ks][2] = *(const uint32_t*)&Qfg[(size_t)ra * 64 + d0 + 8];
            Qa[ks][3] = *(const uint32_t*)&Qfg[(size_t)(ra + 8) * 64 + d0 + 8];
        }
    }

    float o[8][4] = {};
    float l0 = 0.0f, l1 = 0.0f;

    const int nkt    = qt + 1;
    const int my_nkt = ((wq + 15) >> 7) + 1;

    // prefetch: 2 tiles (Kf,Vf) x 128 rows x 8 chunks = 2048 chunks / 256 thr
    auto prefetch = [&](int kt, int bufb) {
        #pragma unroll
        for (int j = 0; j < 8; j++) {
            const int tile = j >> 2;
            int c   = (j & 3) * 256 + tid;
            int row = c >> 3, ch = c & 7;
            const __half* src = (tile == 0 ? Kfg : Vfg)
                + (size_t)(kt * 128 + row) * 64 + ch * 8;
            uint32_t dst = smb + bufb * FBUF + tile * 16384 + row * 128
                         + ((ch ^ (row & 7)) << 4);
            cp16(dst, src);
        }
    };

    prefetch(0, 0);
    CP_COMMIT();

    for (int kt = 0; kt < nkt; kt++) {
        const int buf = kt & 1;
        if (kt + 1 < nkt) prefetch(kt + 1, buf ^ 1);
        CP_COMMIT();
        CP_WAIT1();
        __syncthreads();

        if (kt < my_nkt) {
            const uint32_t bKf = smb + buf * FBUF;
            const uint32_t bVf = bKf + 16384;

            // ---- S = Q K^T (fp16), log2 scale ----
            float s[16][4] = {};
            #pragma unroll
            for (int ks = 0; ks < 4; ks++) {
                #pragma unroll
                for (int ntp = 0; ntp < 8; ntp++) {
                    int mat  = lane >> 3;
                    int key  = ntp * 16 + (mat >> 1) * 8 + (lane & 7);
                    int ch   = 2 * ks + (mat & 1);
                    uint32_t off = key * 128 + (((ch ^ (key & 7))) << 4);
                    uint32_t kf[4];
                    ldmx4(kf, bKf + off);
                    mma_fp16(s[2*ntp],   Qa[ks], kf);
                    mma_fp16(s[2*ntp+1], Qa[ks], kf + 2);
                }
            }

            // ---- causal mask ----
            if ((kt << 7) + 127 > wq) {
                int q0 = wq + (lane >> 2), q1 = q0 + 8;
                #pragma unroll
                for (int nt = 0; nt < 16; nt++) {
                    int key = (kt << 7) + nt * 8 + ((lane & 3) << 1);
                    if (key     > q0) s[nt][0] = -1e30f;
                    if (key + 1 > q0) s[nt][1] = -1e30f;
                    if (key     > q1) s[nt][2] = -1e30f;
                    if (key + 1 > q1) s[nt][3] = -1e30f;
                }
            }

            // ---- p = exp2(s), lane-local sums ----
            #pragma unroll
            for (int nt = 0; nt < 16; nt++) {
                float p0 = exp2p(s[nt][0]);
                float p1 = exp2p(s[nt][1]);
                float p2 = exp2p(s[nt][2]);
                float p3 = exp2p(s[nt][3]);
                s[nt][0] = p0; s[nt][1] = p1; s[nt][2] = p2; s[nt][3] = p3;
                l0 += p0 + p1;
                l1 += p2 + p3;
            }

            // ---- O += P V (fp16) ----
            #pragma unroll
            for (int ks = 0; ks < 8; ks++) {
                uint32_t Pf[4];
                Pf[0] = h2pack(s[2*ks][0],   s[2*ks][1]);
                Pf[1] = h2pack(s[2*ks][2],   s[2*ks][3]);
                Pf[2] = h2pack(s[2*ks+1][0], s[2*ks+1][1]);
                Pf[3] = h2pack(s[2*ks+1][2], s[2*ks+1][3]);
                #pragma unroll
                for (int ntp = 0; ntp < 4; ntp++) {
                    int mat = lane >> 3;
                    int kk  = ks * 16 + (mat & 1) * 8 + (lane & 7);
                    int ch  = ntp * 2 + (mat >> 1);
                    uint32_t off = kk * 128 + (((ch ^ (kk & 7))) << 4);
                    uint32_t vf[4];
                    ldmx4t(vf, bVf + off);
                    mma_fp16(o[2*ntp],   Pf, vf);
                    mma_fp16(o[2*ntp+1], Pf, vf + 2);
                }
            }
        }
        __syncthreads();
    }

    l0 += __shfl_xor_sync(0xffffffffu, l0, 1);
    l0 += __shfl_xor_sync(0xffffffffu, l0, 2);
    l1 += __shfl_xor_sync(0xffffffffu, l1, 1);
    l1 += __shfl_xor_sync(0xffffffffu, l1, 2);

    // ---- epilogue: normalize, write fp16 ctx [b,l,d] ----
    const int b = bh >> 4, hdh = bh & 15;
    const int q0 = wq + (lane >> 2), q1 = q0 + 8;
    float inv0 = 1.0f / l0, inv1 = 1.0f / l1;
    #pragma unroll
    for (int nt = 0; nt < 8; nt++) {
        int d = nt * 8 + ((lane & 3) << 1);
        size_t o0 = (size_t)(b * LL + q0) * DD + hdh * 64 + d;
        size_t o1 = (size_t)(b * LL + q1) * DD + hdh * 64 + d;
        *(uint32_t*)&ctxf[o0] = h2pack(o[nt][0] * inv0, o[nt][1] * inv0);
        *(uint32_t*)&ctxf[o1] = h2pack(o[nt][2] * inv1, o[nt][3] * inv1);
    }
}

// ---------------------------------------------------------------------------
extern "C" void kernel_launch(void* const* d_in, const int* in_sizes, int n_in,
                              void* d_out, int out_size)
{
    const float* x      = (const float*)d_in[0];
    // d_in[1] = causal mask (tril) — causality applied analytically, unused
    const float* Wq     = (const float*)d_in[2];
    const float* Wk     = (const float*)d_in[3];
    const float* Wv     = (const float*)d_in[4];
    const float* Wo     = (const float*)d_in[5];
    const float* qgamma = (const float*)d_in[6];
    const float* qbeta  = (const float*)d_in[7];
    const float* kgamma = (const float*)d_in[8];
    const float* kbeta  = (const float*)d_in[9];
    float* out = (float*)d_out;

    float *dQ, *dK;
    __half *dxf, *dWq16, *dWk16, *dWv16, *dWo16, *dCf, *dVf, *dQf, *dKf;
    cudaGetSymbolAddress((void**)&dQ,  g_Q);
    cudaGetSymbolAddress((void**)&dK,  g_K);
    cudaGetSymbolAddress((void**)&dxf, g_xf);
    cudaGetSymbolAddress((void**)&dCf, g_Cf);
    cudaGetSymbolAddress((void**)&dVf, g_Vf);
    cudaGetSymbolAddress((void**)&dQf, g_Qf);
    cudaGetSymbolAddress((void**)&dKf, g_Kf);
    cudaGetSymbolAddress((void**)&dWq16, g_Wq16);
    cudaGetSymbolAddress((void**)&dWk16, g_Wk16);
    cudaGetSymbolAddress((void**)&dWv16, g_Wv16);
    cudaGetSymbolAddress((void**)&dWo16, g_Wo16);

    const int gemm_smem  = 2 * GBUF;   // 64 KB
    const int flash_smem = 2 * FBUF;   // 64 KB
    cudaFuncSetAttribute(gemm_fp16,
                         cudaFuncAttributeMaxDynamicSharedMemorySize, gemm_smem);
    cudaFuncSetAttribute(flash_mma,
                         cudaFuncAttributeMaxDynamicSharedMemorySize, flash_smem);

    // fp16 operand conversion
    tohalf<<<NEL / 1024, 256>>>(x, dxf);
    tohalf_w4<<<4 * (DD * DD / 1024), 256>>>(Wq, Wk, Wv, Wo,
                                             dWq16, dWk16, dWv16, dWo16);

    dim3 gg(DD / 128, NTOK / 128);   // (8, 64)

    gemm_fp16<<<gg, 128, gemm_smem>>>(dxf, dWq16, dQ, nullptr, 1);
    gemm_fp16<<<gg, 128, gemm_smem>>>(dxf, dWk16, dK, nullptr, 1);
    gemm_fp16<<<gg, 128, gemm_smem>>>(dxf, dWv16, nullptr, dVf, 2);

    ln_head_f16<<<(BB * HH * LL) / 8, 256>>>(dQ, qgamma, qbeta, dQf, CS);
    ln_head_f16<<<(BB * HH * LL) / 8, 256>>>(dK, kgamma, kbeta, dKf, 1.0f);

    flash_mma<<<dim3(BB * HH, LL / 128), 256, flash_smem>>>(dQf, dKf, dVf, dCf);

    gemm_fp16<<<gg, 128, gemm_smem>>>(dCf, dWo16, out, nullptr, 0);
}

// round 16
// speedup vs baseline: 2.7604x; 1.1566x over previous
#include <cuda_runtime.h>
#include <cuda_fp16.h>
#include <math.h>
#include <stdint.h>

#define BB 4
#define LL 2048
#define DD 1024
#define HH 16
#define HDD 64
#define NTOK (BB*LL)            // 8192 rows
#define NEL  (BB*HH*LL*HDD)     // 8.4M elements

// Scratch (device globals — no allocations allowed)
__device__ __align__(16) __half g_xf[NEL];          // x fp16
__device__ __align__(16) __half g_Wq16[DD*DD], g_Wk16[DD*DD];
__device__ __align__(16) __half g_Wv16[DD*DD], g_Wo16[DD*DD];
__device__ __align__(16) __half g_Cf[NEL];          // ctx fp16
__device__ __align__(16) __half g_Vf[NEL];          // V fp16 head-major
__device__ __align__(16) __half g_Qf[NEL];          // Q fp16 post-LN (CS folded)
__device__ __align__(16) __half g_Kf[NEL];          // K fp16 post-LN

// ===========================================================================
// helpers
// ===========================================================================
__device__ __forceinline__ uint32_t smem_u32(const void* p) {
    uint32_t a;
    asm("{ .reg .u64 t; cvta.to.shared.u64 t, %1; cvt.u32.u64 %0, t; }"
        : "=r"(a) : "l"(p));
    return a;
}

__device__ __forceinline__ void mma_fp16(float* c, const uint32_t* a, const uint32_t* b) {
    asm volatile(
        "mma.sync.aligned.m16n8k16.row.col.f32.f16.f16.f32 "
        "{%0,%1,%2,%3}, {%4,%5,%6,%7}, {%8,%9}, {%0,%1,%2,%3};"
        : "+f"(c[0]), "+f"(c[1]), "+f"(c[2]), "+f"(c[3])
        : "r"(a[0]), "r"(a[1]), "r"(a[2]), "r"(a[3]), "r"(b[0]), "r"(b[1]));
}

__device__ __forceinline__ void ldmx4(uint32_t* r, uint32_t addr) {
    asm volatile("ldmatrix.sync.aligned.m8n8.x4.shared.b16 {%0,%1,%2,%3}, [%4];"
                 : "=r"(r[0]), "=r"(r[1]), "=r"(r[2]), "=r"(r[3]) : "r"(addr));
}
__device__ __forceinline__ void ldmx4t(uint32_t* r, uint32_t addr) {
    asm volatile("ldmatrix.sync.aligned.m8n8.x4.trans.shared.b16 {%0,%1,%2,%3}, [%4];"
                 : "=r"(r[0]), "=r"(r[1]), "=r"(r[2]), "=r"(r[3]) : "r"(addr));
}

__device__ __forceinline__ void cp16(uint32_t dst, const void* src) {
    asm volatile("cp.async.cg.shared.global [%0], [%1], 16;" :: "r"(dst), "l"(src));
}
#define CP_COMMIT() asm volatile("cp.async.commit_group;" ::: "memory")
#define CP_WAIT1()  asm volatile("cp.async.wait_group 1;" ::: "memory")

__device__ __forceinline__ uint32_t h2pack(float a, float b) {
    __half2 h = __floats2half2_rn(a, b);
    return *(uint32_t*)&h;
}

// fast 2^t on FMA/ALU pipes (no MUFU). clamped at -100; t <= ~12 here.
__device__ __forceinline__ float exp2p(float t) {
    t = fmaxf(t, -100.0f);
    float z = t + 12582912.0f;
    float f = t - (z - 12582912.0f);
    float p =             1.3333558e-3f;
    p = fmaf(p, f, 9.6181291e-3f);
    p = fmaf(p, f, 5.5504109e-2f);
    p = fmaf(p, f, 2.4022651e-1f);
    p = fmaf(p, f, 6.9314718e-1f);
    p = fmaf(p, f, 1.0f);
    return __int_as_float(__float_as_int(p) + (__float_as_int(z) << 23));
}

// ---------------------------------------------------------------------------
// fp32 -> fp16 converters
// ---------------------------------------------------------------------------
__global__ __launch_bounds__(256) void tohalf(const float* __restrict__ X,
                                              __half* __restrict__ Y)
{
    int i = blockIdx.x * 256 + threadIdx.x;
    float4 v = ((const float4*)X)[i];
    ((uint2*)Y)[i] = make_uint2(h2pack(v.x, v.y), h2pack(v.z, v.w));
}

__global__ __launch_bounds__(256) void tohalf_w4(const float* __restrict__ W0,
                                                 const float* __restrict__ W1,
                                                 const float* __restrict__ W2,
                                                 const float* __restrict__ W3,
                                                 __half* __restrict__ Y0,
                                                 __half* __restrict__ Y1,
                                                 __half* __restrict__ Y2,
                                                 __half* __restrict__ Y3)
{
    int which = blockIdx.x >> 10;
    int i = (blockIdx.x & 1023) * 256 + threadIdx.x;
    const float* W = which == 0 ? W0 : which == 1 ? W1 : which == 2 ? W2 : W3;
    __half* Y = which == 0 ? Y0 : which == 1 ? Y1 : which == 2 ? Y2 : Y3;
    float4 v = ((const float4*)W)[i];
    ((uint2*)Y)[i] = make_uint2(h2pack(v.x, v.y), h2pack(v.z, v.w));
}

// ===========================================================================
// Fused QKV projection + per-head LayerNorm, one launch.
// grid (24, 64): blockIdx.x>>3 selects {Q,K,V}; (blockIdx.x&7)*128 = n0.
// CTA 128x128, BK=64, 4 warps of 64x64. Warp tile N width (64) == head dim,
// so each output row's head lives in one warp quad -> LN = 2 shfl per row.
// Q path: LN with CS folded; K path: LN; V path: plain fp16 convert.
// ===========================================================================
#define GBUF 32768
#define CS 0.18033688f   // 0.125 * log2(e)

__global__ __launch_bounds__(128, 2) void gemm_qkv(
    const __half* __restrict__ A,
    const __half* __restrict__ Wq, const __half* __restrict__ Wk,
    const __half* __restrict__ Wv,
    __half* __restrict__ Qf, __half* __restrict__ Kf, __half* __restrict__ Vf,
    const float* __restrict__ qgamma, const float* __restrict__ qbeta,
    const float* __restrict__ kgamma, const float* __restrict__ kbeta)
{
    extern __shared__ char gsm[];
    const uint32_t smb = smem_u32(gsm);
    const int tid  = threadIdx.x;
    const int lane = tid & 31;
    const int wid  = tid >> 5;
    const int wm0  = (wid & 1) * 64;
    const int wn0  = (wid >> 1) * 64;
    const int which = blockIdx.x >> 3;
    const int n0   = (blockIdx.x & 7) * 128;
    const int m0   = blockIdx.y * 128;
    const int mat  = lane >> 3;

    const __half* B = which == 0 ? Wq : which == 1 ? Wk : Wv;
    __half* OUT     = which == 0 ? Qf : which == 1 ? Kf : Vf;

    float acc[4][8][4] = {};

    auto prefetch = [&](int kc, int b) {
        #pragma unroll
        for (int j = 0; j < 16; j++) {
            const int tile = j >> 3;
            int c   = (j & 7) * 128 + tid;
            int row = c >> 3, ch = c & 7;
            int grow = (tile == 0 ? m0 : n0) + row;
            const __half* src = (tile == 0 ? A : B) + (size_t)grow * DD + kc * 64 + ch * 8;
            uint32_t dst = smb + b * GBUF + tile * 16384 + row * 128
                         + ((ch ^ (row & 7)) << 4);
            cp16(dst, src);
        }
    };

    prefetch(0, 0);
    CP_COMMIT();

    for (int kc = 0; kc < 16; kc++) {
        const int buf = kc & 1;
        if (kc + 1 < 16) prefetch(kc + 1, buf ^ 1);
        CP_COMMIT();
        CP_WAIT1();
        __syncthreads();

        const uint32_t bA = smb + buf * GBUF;
        const uint32_t bB = bA + 16384;

        #pragma unroll
        for (int ks = 0; ks < 4; ks++) {
            uint32_t aF[4][4];
            #pragma unroll
            for (int mt = 0; mt < 4; mt++) {
                int r  = wm0 + mt * 16 + ((mat & 1) << 3) + (lane & 7);
                int ch = 2 * ks + (mat >> 1);
                uint32_t off = r * 128 + ((ch ^ (r & 7)) << 4);
                ldmx4(aF[mt], bA + off);
            }
            uint32_t bF[4][4];
            #pragma unroll
            for (int np = 0; np < 4; np++) {
                int rn = wn0 + np * 16 + ((mat >> 1) << 3) + (lane & 7);
                int ch = 2 * ks + (mat & 1);
                uint32_t off = rn * 128 + ((ch ^ (rn & 7)) << 4);
                ldmx4(bF[np], bB + off);
            }
            #pragma unroll
            for (int mt = 0; mt < 4; mt++)
                #pragma unroll
                for (int np = 0; np < 4; np++) {
                    mma_fp16(acc[mt][2*np],   aF[mt], bF[np]);
                    mma_fp16(acc[mt][2*np+1], aF[mt], bF[np] + 2);
                }
        }
        __syncthreads();
    }

    // ---- epilogue: fused per-head LN (Q,K) or plain convert (V) ----
    const int hh   = (n0 + wn0) >> 6;        // global head index
    const int cbase = (lane & 3) << 1;       // this thread's first col in head
    const float scale = (which == 0) ? CS : 1.0f;
    const bool doln = (which < 2);
    const float* gamma = (which == 0) ? qgamma : kgamma;
    const float* beta  = (which == 0) ? qbeta  : kbeta;

    float gv[8][2], bv[8][2];
    if (doln) {
        #pragma unroll
        for (int nt = 0; nt < 8; nt++) {
            int c = cbase + nt * 8;
            gv[nt][0] = gamma[c] * scale;     gv[nt][1] = gamma[c + 1] * scale;
            bv[nt][0] = beta[c]  * scale;     bv[nt][1] = beta[c + 1]  * scale;
        }
    }

    #pragma unroll
    for (int mt = 0; mt < 4; mt++) {
        #pragma unroll
        for (int hf = 0; hf < 2; hf++) {
            int r = m0 + wm0 + mt * 16 + (lane >> 2) + hf * 8;
            int bI = r >> 11, l = r & (LL - 1);
            size_t rowoff = ((size_t)((bI * HH + hh) * LL + l) << 6);

            if (doln) {
                float s = 0.0f, sq = 0.0f;
                #pragma unroll
                for (int nt = 0; nt < 8; nt++) {
                    float v0 = acc[mt][nt][2*hf], v1 = acc[mt][nt][2*hf + 1];
                    s  += v0 + v1;
                    sq += v0 * v0 + v1 * v1;
                }
                s  += __shfl_xor_sync(0xffffffffu, s,  1);
                s  += __shfl_xor_sync(0xffffffffu, s,  2);
                sq += __shfl_xor_sync(0xffffffffu, sq, 1);
                sq += __shfl_xor_sync(0xffffffffu, sq, 2);
                float mean = s * (1.0f / 64.0f);
                float var  = sq * (1.0f / 64.0f) - mean * mean;
                float inv  = rsqrtf(var + 1e-5f);
                #pragma unroll
                for (int nt = 0; nt < 8; nt++) {
                    float v0 = (acc[mt][nt][2*hf]     - mean) * (inv * gv[nt][0]) + bv[nt][0];
                    float v1 = (acc[mt][nt][2*hf + 1] - mean) * (inv * gv[nt][1]) + bv[nt][1];
                    *(uint32_t*)&OUT[rowoff + cbase + nt * 8] = h2pack(v0, v1);
                }
            } else {
                #pragma unroll
                for (int nt = 0; nt < 8; nt++) {
                    *(uint32_t*)&OUT[rowoff + cbase + nt * 8] =
                        h2pack(acc[mt][nt][2*hf], acc[mt][nt][2*hf + 1]);
                }
            }
        }
    }
}

// ===========================================================================
// fp16 out-projection GEMM: out[M,1024] = ctx @ Wo^T (fp32 row-major out)
// ===========================================================================
__global__ __launch_bounds__(128, 2) void gemm_out(const __half* __restrict__ A,
                                                   const __half* __restrict__ B,
                                                   float* __restrict__ C)
{
    extern __shared__ char gsm[];
    const uint32_t smb = smem_u32(gsm);
    const int tid  = threadIdx.x;
    const int lane = tid & 31;
    const int wid  = tid >> 5;
    const int wm0  = (wid & 1) * 64;
    const int wn0  = (wid >> 1) * 64;
    const int m0   = blockIdx.y * 128;
    const int n0   = blockIdx.x * 128;
    const int mat  = lane >> 3;

    float acc[4][8][4] = {};

    auto prefetch = [&](int kc, int b) {
        #pragma unroll
        for (int j = 0; j < 16; j++) {
            const int tile = j >> 3;
            int c   = (j & 7) * 128 + tid;
            int row = c >> 3, ch = c & 7;
            int grow = (tile == 0 ? m0 : n0) + row;
            const __half* src = (tile == 0 ? A : B) + (size_t)grow * DD + kc * 64 + ch * 8;
            uint32_t dst = smb + b * GBUF + tile * 16384 + row * 128
                         + ((ch ^ (row & 7)) << 4);
            cp16(dst, src);
        }
    };

    prefetch(0, 0);
    CP_COMMIT();

    for (int kc = 0; kc < 16; kc++) {
        const int buf = kc & 1;
        if (kc + 1 < 16) prefetch(kc + 1, buf ^ 1);
        CP_COMMIT();
        CP_WAIT1();
        __syncthreads();

        const uint32_t bA = smb + buf * GBUF;
        const uint32_t bB = bA + 16384;

        #pragma unroll
        for (int ks = 0; ks < 4; ks++) {
            uint32_t aF[4][4];
            #pragma unroll
            for (int mt = 0; mt < 4; mt++) {
                int r  = wm0 + mt * 16 + ((mat & 1) << 3) + (lane & 7);
                int ch = 2 * ks + (mat >> 1);
                uint32_t off = r * 128 + ((ch ^ (r & 7)) << 4);
                ldmx4(aF[mt], bA + off);
            }
            uint32_t bF[4][4];
            #pragma unroll
            for (int np = 0; np < 4; np++) {
                int rn = wn0 + np * 16 + ((mat >> 1) << 3) + (lane & 7);
                int ch = 2 * ks + (mat & 1);
                uint32_t off = rn * 128 + ((ch ^ (rn & 7)) << 4);
                ldmx4(bF[np], bB + off);
            }
            #pragma unroll
            for (int mt = 0; mt < 4; mt++)
                #pragma unroll
                for (int np = 0; np < 4; np++) {
                    mma_fp16(acc[mt][2*np],   aF[mt], bF[np]);
                    mma_fp16(acc[mt][2*np+1], aF[mt], bF[np] + 2);
                }
        }
        __syncthreads();
    }

    #pragma unroll
    for (int mt = 0; mt < 4; mt++) {
        #pragma unroll
        for (int nt = 0; nt < 8; nt++) {
            int row = m0 + wm0 + mt * 16 + (lane >> 2);
            int col = n0 + wn0 + nt * 8 + ((lane & 3) << 1);
            #pragma unroll
            for (int hf = 0; hf < 2; hf++) {
                int r = row + hf * 8;
                *(float2*)&C[(size_t)r * DD + col] =
                    make_float2(acc[mt][nt][2*hf], acc[mt][nt][2*hf + 1]);
            }
        }
    }
}

// ===========================================================================
// Tensor-core causal flash attention, ALL fp16 single-mma.
// 8 warps x 16 Q-rows, BK=128. Buffers {Kf,Vf} = 32KB; x2 = 64KB smem.
// ===========================================================================
#define FBUF 32768       // bytes per flash buffer

__global__ __launch_bounds__(256, 1) void flash_mma(
    const __half* __restrict__ Qf, const __half* __restrict__ Kf,
    const __half* __restrict__ Vf,
    __half* __restrict__ ctxf)
{
    extern __shared__ char fsm[];
    const uint32_t smb = smem_u32(fsm);
    const int tid  = threadIdx.x;
    const int lane = tid & 31;
    const int w    = tid >> 5;
    const int bh   = blockIdx.x;
    const int qt   = (gridDim.y - 1) - blockIdx.y;   // heavy CTAs first

    const __half* Qfg = Qf + (size_t)bh * LL * HDD;
    const __half* Kfg = Kf + (size_t)bh * LL * HDD;
    const __half* Vfg = Vf + (size_t)bh * LL * HDD;

    const int wq = qt * 128 + w * 16;

    uint32_t Qa[4][4];
    {
        int ra = wq + (lane >> 2);
        #pragma unroll
        for (int ks = 0; ks < 4; ks++) {
            int d0 = ks * 16 + (lane & 3) * 2;
            Qa[ks][0] = *(const uint32_t*)&Qfg[(size_t)ra * 64 + d0];
            Qa[ks][1] = *(const uint32_t*)&Qfg[(size_t)(ra + 8) * 64 + d0];
            Qa[ks][2] = *(const uint32_t*)&Qfg[(size_t)ra * 64 + d0 + 8];
            Qa[ks][3] = *(const uint32_t*)&Qfg[(size_t)(ra + 8) * 64 + d0 + 8];
        }
    }

    float o[8][4] = {};
    float l0 = 0.0f, l1 = 0.0f;

    const int nkt    = qt + 1;
    const int my_nkt = ((wq + 15) >> 7) + 1;

    auto prefetch = [&](int kt, int bufb) {
        #pragma unroll
        for (int j = 0; j < 8; j++) {
            const int tile = j >> 2;
            int c   = (j & 3) * 256 + tid;
            int row = c >> 3, ch = c & 7;
            const __half* src = (tile == 0 ? Kfg : Vfg)
                + (size_t)(kt * 128 + row) * 64 + ch * 8;
            uint32_t dst = smb + bufb * FBUF + tile * 16384 + row * 128
                         + ((ch ^ (row & 7)) << 4);
            cp16(dst, src);
        }
    };

    prefetch(0, 0);
    CP_COMMIT();

    for (int kt = 0; kt < nkt; kt++) {
        const int buf = kt & 1;
        if (kt + 1 < nkt) prefetch(kt + 1, buf ^ 1);
        CP_COMMIT();
        CP_WAIT1();
        __syncthreads();

        if (kt < my_nkt) {
            const uint32_t bKf = smb + buf * FBUF;
            const uint32_t bVf = bKf + 16384;

            float s[16][4] = {};
            #pragma unroll
            for (int ks = 0; ks < 4; ks++) {
                #pragma unroll
                for (int ntp = 0; ntp < 8; ntp++) {
                    int mat  = lane >> 3;
                    int key  = ntp * 16 + (mat >> 1) * 8 + (lane & 7);
                    int ch   = 2 * ks + (mat & 1);
                    uint32_t off = key * 128 + (((ch ^ (key & 7))) << 4);
                    uint32_t kf[4];
                    ldmx4(kf, bKf + off);
                    mma_fp16(s[2*ntp],   Qa[ks], kf);
                    mma_fp16(s[2*ntp+1], Qa[ks], kf + 2);
                }
            }

            if ((kt << 7) + 127 > wq) {
                int q0 = wq + (lane >> 2), q1 = q0 + 8;
                #pragma unroll
                for (int nt = 0; nt < 16; nt++) {
                    int key = (kt << 7) + nt * 8 + ((lane & 3) << 1);
                    if (key     > q0) s[nt][0] = -1e30f;
                    if (key + 1 > q0) s[nt][1] = -1e30f;
                    if (key     > q1) s[nt][2] = -1e30f;
                    if (key + 1 > q1) s[nt][3] = -1e30f;
                }
            }

            #pragma unroll
            for (int nt = 0; nt < 16; nt++) {
                float p0 = exp2p(s[nt][0]);
                float p1 = exp2p(s[nt][1]);
                float p2 = exp2p(s[nt][2]);
                float p3 = exp2p(s[nt][3]);
                s[nt][0] = p0; s[nt][1] = p1; s[nt][2] = p2; s[nt][3] = p3;
                l0 += p0 + p1;
                l1 += p2 + p3;
            }

            #pragma unroll
            for (int ks = 0; ks < 8; ks++) {
                uint32_t Pf[4];
                Pf[0] = h2pack(s[2*ks][0],   s[2*ks][1]);
                Pf[1] = h2pack(s[2*ks][2],   s[2*ks][3]);
                Pf[2] = h2pack(s[2*ks+1][0], s[2*ks+1][1]);
                Pf[3] = h2pack(s[2*ks+1][2], s[2*ks+1][3]);
                #pragma unroll
                for (int ntp = 0; ntp < 4; ntp++) {
                    int mat = lane >> 3;
                    int kk  = ks * 16 + (mat & 1) * 8 + (lane & 7);
                    int ch  = ntp * 2 + (mat >> 1);
                    uint32_t off = kk * 128 + (((ch ^ (kk & 7))) << 4);
                    uint32_t vf[4];
                    ldmx4t(vf, bVf + off);
                    mma_fp16(o[2*ntp],   Pf, vf);
                    mma_fp16(o[2*ntp+1], Pf, vf + 2);
                }
            }
        }
        __syncthreads();
    }

    l0 += __shfl_xor_sync(0xffffffffu, l0, 1);
    l0 += __shfl_xor_sync(0xffffffffu, l0, 2);
    l1 += __shfl_xor_sync(0xffffffffu, l1, 1);
    l1 += __shfl_xor_sync(0xffffffffu, l1, 2);

    const int b = bh >> 4, hdh = bh & 15;
    const int q0 = wq + (lane >> 2), q1 = q0 + 8;
    float inv0 = 1.0f / l0, inv1 = 1.0f / l1;
    #pragma unroll
    for (int nt = 0; nt < 8; nt++) {
        int d = nt * 8 + ((lane & 3) << 1);
        size_t o0 = (size_t)(b * LL + q0) * DD + hdh * 64 + d;
        size_t o1 = (size_t)(b * LL + q1) * DD + hdh * 64 + d;
        *(uint32_t*)&ctxf[o0] = h2pack(o[nt][0] * inv0, o[nt][1] * inv0);
        *(uint32_t*)&ctxf[o1] = h2pack(o[nt][2] * inv1, o[nt][3] * inv1);
    }
}

// ---------------------------------------------------------------------------
extern "C" void kernel_launch(void* const* d_in, const int* in_sizes, int n_in,
                              void* d_out, int out_size)
{
    const float* x      = (const float*)d_in[0];
    // d_in[1] = causal mask (tril) — causality applied analytically, unused
    const float* Wq     = (const float*)d_in[2];
    const float* Wk     = (const float*)d_in[3];
    const float* Wv     = (const float*)d_in[4];
    const float* Wo     = (const float*)d_in[5];
    const float* qgamma = (const float*)d_in[6];
    const float* qbeta  = (const float*)d_in[7];
    const float* kgamma = (const float*)d_in[8];
    const float* kbeta  = (const float*)d_in[9];
    float* out = (float*)d_out;

    __half *dxf, *dWq16, *dWk16, *dWv16, *dWo16, *dCf, *dVf, *dQf, *dKf;
    cudaGetSymbolAddress((void**)&dxf, g_xf);
    cudaGetSymbolAddress((void**)&dCf, g_Cf);
    cudaGetSymbolAddress((void**)&dVf, g_Vf);
    cudaGetSymbolAddress((void**)&dQf, g_Qf);
    cudaGetSymbolAddress((void**)&dKf, g_Kf);
    cudaGetSymbolAddress((void**)&dWq16, g_Wq16);
    cudaGetSymbolAddress((void**)&dWk16, g_Wk16);
    cudaGetSymbolAddress((void**)&dWv16, g_Wv16);
    cudaGetSymbolAddress((void**)&dWo16, g_Wo16);

    const int gemm_smem  = 2 * GBUF;   // 64 KB
    const int flash_smem = 2 * FBUF;   // 64 KB
    cudaFuncSetAttribute(gemm_qkv,
                         cudaFuncAttributeMaxDynamicSharedMemorySize, gemm_smem);
    cudaFuncSetAttribute(gemm_out,
                         cudaFuncAttributeMaxDynamicSharedMemorySize, gemm_smem);
    cudaFuncSetAttribute(flash_mma,
                         cudaFuncAttributeMaxDynamicSharedMemorySize, flash_smem);

    // fp16 operand conversion
    tohalf<<<NEL / 1024, 256>>>(x, dxf);
    tohalf_w4<<<4 * (DD * DD / 1024), 256>>>(Wq, Wk, Wv, Wo,
                                             dWq16, dWk16, dWv16, dWo16);

    // fused QKV projection + LN (one launch, 1536 CTAs)
    gemm_qkv<<<dim3(24, NTOK / 128), 128, gemm_smem>>>(
        dxf, dWq16, dWk16, dWv16, dQf, dKf, dVf,
        qgamma, qbeta, kgamma, kbeta);

    flash_mma<<<dim3(BB * HH, LL / 128), 256, flash_smem>>>(dQf, dKf, dVf, dCf);

    gemm_out<<<dim3(DD / 128, NTOK / 128), 128, gemm_smem>>>(dCf, dWo16, out);
}

// round 17
// speedup vs baseline: 2.9322x; 1.0622x over previous
#include <cuda_runtime.h>
#include <cuda_fp16.h>
#include <math.h>
#include <stdint.h>

#define BB 4
#define LL 2048
#define DD 1024
#define HH 16
#define HDD 64
#define NTOK (BB*LL)            // 8192 rows
#define NEL  (BB*HH*LL*HDD)     // 8.4M elements

// Scratch (device globals — no allocations allowed)
__device__ __align__(16) __half g_xf[NEL];          // x fp16
__device__ __align__(16) __half g_Wq16[DD*DD], g_Wk16[DD*DD];
__device__ __align__(16) __half g_Wv16[DD*DD], g_Wo16[DD*DD];
__device__ __align__(16) __half g_Cf[NEL];          // ctx fp16
__device__ __align__(16) __half g_Vf[NEL];          // V fp16 head-major
__device__ __align__(16) __half g_Qf[NEL];          // Q fp16 post-LN (CS folded)
__device__ __align__(16) __half g_Kf[NEL];          // K fp16 post-LN

// ===========================================================================
// helpers
// ===========================================================================
__device__ __forceinline__ uint32_t smem_u32(const void* p) {
    uint32_t a;
    asm("{ .reg .u64 t; cvta.to.shared.u64 t, %1; cvt.u32.u64 %0, t; }"
        : "=r"(a) : "l"(p));
    return a;
}

__device__ __forceinline__ void mma_fp16(float* c, const uint32_t* a, const uint32_t* b) {
    asm volatile(
        "mma.sync.aligned.m16n8k16.row.col.f32.f16.f16.f32 "
        "{%0,%1,%2,%3}, {%4,%5,%6,%7}, {%8,%9}, {%0,%1,%2,%3};"
        : "+f"(c[0]), "+f"(c[1]), "+f"(c[2]), "+f"(c[3])
        : "r"(a[0]), "r"(a[1]), "r"(a[2]), "r"(a[3]), "r"(b[0]), "r"(b[1]));
}

__device__ __forceinline__ void ldmx4(uint32_t* r, uint32_t addr) {
    asm volatile("ldmatrix.sync.aligned.m8n8.x4.shared.b16 {%0,%1,%2,%3}, [%4];"
                 : "=r"(r[0]), "=r"(r[1]), "=r"(r[2]), "=r"(r[3]) : "r"(addr));
}
__device__ __forceinline__ void ldmx4t(uint32_t* r, uint32_t addr) {
    asm volatile("ldmatrix.sync.aligned.m8n8.x4.trans.shared.b16 {%0,%1,%2,%3}, [%4];"
                 : "=r"(r[0]), "=r"(r[1]), "=r"(r[2]), "=r"(r[3]) : "r"(addr));
}

__device__ __forceinline__ void cp16(uint32_t dst, const void* src) {
    asm volatile("cp.async.cg.shared.global [%0], [%1], 16;" :: "r"(dst), "l"(src));
}
#define CP_COMMIT() asm volatile("cp.async.commit_group;" ::: "memory")
#define CP_WAIT1()  asm volatile("cp.async.wait_group 1;" ::: "memory")

__device__ __forceinline__ uint32_t h2pack(float a, float b) {
    __half2 h = __floats2half2_rn(a, b);
    return *(uint32_t*)&h;
}

// fast 2^t, degree-3 poly (max rel err ~2e-5), NO clamp: caller guarantees
// t in [-100, 12].
__device__ __forceinline__ float exp2p(float t) {
    float z = t + 12582912.0f;            // round-to-nearest-int via magic
    float f = t - (z - 12582912.0f);      // f in [-0.5, 0.5]
    float p =             5.550357e-2f;
    p = fmaf(p, f, 2.4022936e-1f);
    p = fmaf(p, f, 6.9314081e-1f);
    p = fmaf(p, f, 9.9999989e-1f);
    return __int_as_float(__float_as_int(p) + (__float_as_int(z) << 23));
}
#define MASKVAL (-100.0f)

// ---------------------------------------------------------------------------
// fp32 -> fp16 converters
// ---------------------------------------------------------------------------
__global__ __launch_bounds__(256) void tohalf(const float* __restrict__ X,
                                              __half* __restrict__ Y)
{
    int i = blockIdx.x * 256 + threadIdx.x;
    float4 v = ((const float4*)X)[i];
    ((uint2*)Y)[i] = make_uint2(h2pack(v.x, v.y), h2pack(v.z, v.w));
}

__global__ __launch_bounds__(256) void tohalf_w4(const float* __restrict__ W0,
                                                 const float* __restrict__ W1,
                                                 const float* __restrict__ W2,
                                                 const float* __restrict__ W3,
                                                 __half* __restrict__ Y0,
                                                 __half* __restrict__ Y1,
                                                 __half* __restrict__ Y2,
                                                 __half* __restrict__ Y3)
{
    int which = blockIdx.x >> 10;
    int i = (blockIdx.x & 1023) * 256 + threadIdx.x;
    const float* W = which == 0 ? W0 : which == 1 ? W1 : which == 2 ? W2 : W3;
    __half* Y = which == 0 ? Y0 : which == 1 ? Y1 : which == 2 ? Y2 : Y3;
    float4 v = ((const float4*)W)[i];
    ((uint2*)Y)[i] = make_uint2(h2pack(v.x, v.y), h2pack(v.z, v.w));
}

// ===========================================================================
// Fused QKV projection + per-head LayerNorm, one launch. (R16, unchanged)
// ===========================================================================
#define GBUF 32768
#define CS 0.18033688f   // 0.125 * log2(e)

__global__ __launch_bounds__(128, 2) void gemm_qkv(
    const __half* __restrict__ A,
    const __half* __restrict__ Wq, const __half* __restrict__ Wk,
    const __half* __restrict__ Wv,
    __half* __restrict__ Qf, __half* __restrict__ Kf, __half* __restrict__ Vf,
    const float* __restrict__ qgamma, const float* __restrict__ qbeta,
    const float* __restrict__ kgamma, const float* __restrict__ kbeta)
{
    extern __shared__ char gsm[];
    const uint32_t smb = smem_u32(gsm);
    const int tid  = threadIdx.x;
    const int lane = tid & 31;
    const int wid  = tid >> 5;
    const int wm0  = (wid & 1) * 64;
    const int wn0  = (wid >> 1) * 64;
    const int which = blockIdx.x >> 3;
    const int n0   = (blockIdx.x & 7) * 128;
    const int m0   = blockIdx.y * 128;
    const int mat  = lane >> 3;

    const __half* B = which == 0 ? Wq : which == 1 ? Wk : Wv;
    __half* OUT     = which == 0 ? Qf : which == 1 ? Kf : Vf;

    float acc[4][8][4] = {};

    auto prefetch = [&](int kc, int b) {
        #pragma unroll
        for (int j = 0; j < 16; j++) {
            const int tile = j >> 3;
            int c   = (j & 7) * 128 + tid;
            int row = c >> 3, ch = c & 7;
            int grow = (tile == 0 ? m0 : n0) + row;
            const __half* src = (tile == 0 ? A : B) + (size_t)grow * DD + kc * 64 + ch * 8;
            uint32_t dst = smb + b * GBUF + tile * 16384 + row * 128
                         + ((ch ^ (row & 7)) << 4);
            cp16(dst, src);
        }
    };

    prefetch(0, 0);
    CP_COMMIT();

    for (int kc = 0; kc < 16; kc++) {
        const int buf = kc & 1;
        if (kc + 1 < 16) prefetch(kc + 1, buf ^ 1);
        CP_COMMIT();
        CP_WAIT1();
        __syncthreads();

        const uint32_t bA = smb + buf * GBUF;
        const uint32_t bB = bA + 16384;

        #pragma unroll
        for (int ks = 0; ks < 4; ks++) {
            uint32_t aF[4][4];
            #pragma unroll
            for (int mt = 0; mt < 4; mt++) {
                int r  = wm0 + mt * 16 + ((mat & 1) << 3) + (lane & 7);
                int ch = 2 * ks + (mat >> 1);
                uint32_t off = r * 128 + ((ch ^ (r & 7)) << 4);
                ldmx4(aF[mt], bA + off);
            }
            uint32_t bF[4][4];
            #pragma unroll
            for (int np = 0; np < 4; np++) {
                int rn = wn0 + np * 16 + ((mat >> 1) << 3) + (lane & 7);
                int ch = 2 * ks + (mat & 1);
                uint32_t off = rn * 128 + ((ch ^ (rn & 7)) << 4);
                ldmx4(bF[np], bB + off);
            }
            #pragma unroll
            for (int mt = 0; mt < 4; mt++)
                #pragma unroll
                for (int np = 0; np < 4; np++) {
                    mma_fp16(acc[mt][2*np],   aF[mt], bF[np]);
                    mma_fp16(acc[mt][2*np+1], aF[mt], bF[np] + 2);
                }
        }
        __syncthreads();
    }

    // ---- epilogue: fused per-head LN (Q,K) or plain convert (V) ----
    const int hh    = (n0 + wn0) >> 6;
    const int cbase = (lane & 3) << 1;
    const float scale = (which == 0) ? CS : 1.0f;
    const bool doln = (which < 2);
    const float* gamma = (which == 0) ? qgamma : kgamma;
    const float* beta  = (which == 0) ? qbeta  : kbeta;

    float gv[8][2], bv[8][2];
    if (doln) {
        #pragma unroll
        for (int nt = 0; nt < 8; nt++) {
            int c = cbase + nt * 8;
            gv[nt][0] = gamma[c] * scale;     gv[nt][1] = gamma[c + 1] * scale;
            bv[nt][0] = beta[c]  * scale;     bv[nt][1] = beta[c + 1]  * scale;
        }
    }

    #pragma unroll
    for (int mt = 0; mt < 4; mt++) {
        #pragma unroll
        for (int hf = 0; hf < 2; hf++) {
            int r = m0 + wm0 + mt * 16 + (lane >> 2) + hf * 8;
            int bI = r >> 11, l = r & (LL - 1);
            size_t rowoff = ((size_t)((bI * HH + hh) * LL + l) << 6);

            if (doln) {
                float s = 0.0f, sq = 0.0f;
                #pragma unroll
                for (int nt = 0; nt < 8; nt++) {
                    float v0 = acc[mt][nt][2*hf], v1 = acc[mt][nt][2*hf + 1];
                    s  += v0 + v1;
                    sq += v0 * v0 + v1 * v1;
                }
                s  += __shfl_xor_sync(0xffffffffu, s,  1);
                s  += __shfl_xor_sync(0xffffffffu, s,  2);
                sq += __shfl_xor_sync(0xffffffffu, sq, 1);
                sq += __shfl_xor_sync(0xffffffffu, sq, 2);
                float mean = s * (1.0f / 64.0f);
                float var  = sq * (1.0f / 64.0f) - mean * mean;
                float inv  = rsqrtf(var + 1e-5f);
                #pragma unroll
                for (int nt = 0; nt < 8; nt++) {
                    float v0 = (acc[mt][nt][2*hf]     - mean) * (inv * gv[nt][0]) + bv[nt][0];
                    float v1 = (acc[mt][nt][2*hf + 1] - mean) * (inv * gv[nt][1]) + bv[nt][1];
                    *(uint32_t*)&OUT[rowoff + cbase + nt * 8] = h2pack(v0, v1);
                }
            } else {
                #pragma unroll
                for (int nt = 0; nt < 8; nt++) {
                    *(uint32_t*)&OUT[rowoff + cbase + nt * 8] =
                        h2pack(acc[mt][nt][2*hf], acc[mt][nt][2*hf + 1]);
                }
            }
        }
    }
}

// ===========================================================================
// fp16 out-projection GEMM (R16, unchanged)
// ===========================================================================
__global__ __launch_bounds__(128, 2) void gemm_out(const __half* __restrict__ A,
                                                   const __half* __restrict__ B,
                                                   float* __restrict__ C)
{
    extern __shared__ char gsm[];
    const uint32_t smb = smem_u32(gsm);
    const int tid  = threadIdx.x;
    const int lane = tid & 31;
    const int wid  = tid >> 5;
    const int wm0  = (wid & 1) * 64;
    const int wn0  = (wid >> 1) * 64;
    const int m0   = blockIdx.y * 128;
    const int n0   = blockIdx.x * 128;
    const int mat  = lane >> 3;

    float acc[4][8][4] = {};

    auto prefetch = [&](int kc, int b) {
        #pragma unroll
        for (int j = 0; j < 16; j++) {
            const int tile = j >> 3;
            int c   = (j & 7) * 128 + tid;
            int row = c >> 3, ch = c & 7;
            int grow = (tile == 0 ? m0 : n0) + row;
            const __half* src = (tile == 0 ? A : B) + (size_t)grow * DD + kc * 64 + ch * 8;
            uint32_t dst = smb + b * GBUF + tile * 16384 + row * 128
                         + ((ch ^ (row & 7)) << 4);
            cp16(dst, src);
        }
    };

    prefetch(0, 0);
    CP_COMMIT();

    for (int kc = 0; kc < 16; kc++) {
        const int buf = kc & 1;
        if (kc + 1 < 16) prefetch(kc + 1, buf ^ 1);
        CP_COMMIT();
        CP_WAIT1();
        __syncthreads();

        const uint32_t bA = smb + buf * GBUF;
        const uint32_t bB = bA + 16384;

        #pragma unroll
        for (int ks = 0; ks < 4; ks++) {
            uint32_t aF[4][4];
            #pragma unroll
            for (int mt = 0; mt < 4; mt++) {
                int r  = wm0 + mt * 16 + ((mat & 1) << 3) + (lane & 7);
                int ch = 2 * ks + (mat >> 1);
                uint32_t off = r * 128 + ((ch ^ (r & 7)) << 4);
                ldmx4(aF[mt], bA + off);
            }
            uint32_t bF[4][4];
            #pragma unroll
            for (int np = 0; np < 4; np++) {
                int rn = wn0 + np * 16 + ((mat >> 1) << 3) + (lane & 7);
                int ch = 2 * ks + (mat & 1);
                uint32_t off = rn * 128 + ((ch ^ (rn & 7)) << 4);
                ldmx4(bF[np], bB + off);
            }
            #pragma unroll
            for (int mt = 0; mt < 4; mt++)
                #pragma unroll
                for (int np = 0; np < 4; np++) {
                    mma_fp16(acc[mt][2*np],   aF[mt], bF[np]);
                    mma_fp16(acc[mt][2*np+1], aF[mt], bF[np] + 2);
                }
        }
        __syncthreads();
    }

    #pragma unroll
    for (int mt = 0; mt < 4; mt++) {
        #pragma unroll
        for (int nt = 0; nt < 8; nt++) {
            int row = m0 + wm0 + mt * 16 + (lane >> 2);
            int col = n0 + wn0 + nt * 8 + ((lane & 3) << 1);
            #pragma unroll
            for (int hf = 0; hf < 2; hf++) {
                int r = row + hf * 8;
                *(float2*)&C[(size_t)r * DD + col] =
                    make_float2(acc[mt][nt][2*hf], acc[mt][nt][2*hf + 1]);
            }
        }
    }
}

// ===========================================================================
// Tensor-core causal flash attention, fp16, BK=64, 2 CTAs/SM.
// 8 warps x 16 Q-rows (BQ=128). Buffers {Kf,Vf} = 16KB; x2 = 32KB/CTA.
// launch_bounds(256,2): target <=128 regs (s[8][4]+o[8][4]+Qa = ~112 live).
// ===========================================================================
#define FBUF 16384       // bytes per flash buffer

__global__ __launch_bounds__(256, 2) void flash_mma(
    const __half* __restrict__ Qf, const __half* __restrict__ Kf,
    const __half* __restrict__ Vf,
    __half* __restrict__ ctxf)
{
    extern __shared__ char fsm[];
    const uint32_t smb = smem_u32(fsm);
    const int tid  = threadIdx.x;
    const int lane = tid & 31;
    const int w    = tid >> 5;
    const int bh   = blockIdx.x;
    const int qt   = (gridDim.y - 1) - blockIdx.y;   // heavy CTAs first

    const __half* Qfg = Qf + (size_t)bh * LL * HDD;
    const __half* Kfg = Kf + (size_t)bh * LL * HDD;
    const __half* Vfg = Vf + (size_t)bh * LL * HDD;

    const int wq = qt * 128 + w * 16;

    uint32_t Qa[4][4];
    {
        int ra = wq + (lane >> 2);
        #pragma unroll
        for (int ks = 0; ks < 4; ks++) {
            int d0 = ks * 16 + (lane & 3) * 2;
            Qa[ks][0] = *(const uint32_t*)&Qfg[(size_t)ra * 64 + d0];
            Qa[ks][1] = *(const uint32_t*)&Qfg[(size_t)(ra + 8) * 64 + d0];
            Qa[ks][2] = *(const uint32_t*)&Qfg[(size_t)ra * 64 + d0 + 8];
            Qa[ks][3] = *(const uint32_t*)&Qfg[(size_t)(ra + 8) * 64 + d0 + 8];
        }
    }

    float o[8][4] = {};
    float l0 = 0.0f, l1 = 0.0f;

    const int nkt    = 2 * (qt + 1);             // 64-key tiles
    const int my_nkt = ((wq + 15) >> 6) + 1;     // warp-level masked-tile skip

    // prefetch: 2 tiles (Kf,Vf) x 64 rows x 8 chunks = 1024 chunks / 256 thr
    auto prefetch = [&](int kt, int bufb) {
        #pragma unroll
        for (int j = 0; j < 4; j++) {
            const int tile = j >> 1;
            int c   = (j & 1) * 256 + tid;
            int row = c >> 3, ch = c & 7;
            const __half* src = (tile == 0 ? Kfg : Vfg)
                + (size_t)(kt * 64 + row) * 64 + ch * 8;
            uint32_t dst = smb + bufb * FBUF + tile * 8192 + row * 128
                         + ((ch ^ (row & 7)) << 4);
            cp16(dst, src);
        }
    };

    prefetch(0, 0);
    CP_COMMIT();

    for (int kt = 0; kt < nkt; kt++) {
        const int buf = kt & 1;
        if (kt + 1 < nkt) prefetch(kt + 1, buf ^ 1);
        CP_COMMIT();
        CP_WAIT1();
        __syncthreads();

        if (kt < my_nkt) {
            const uint32_t bKf = smb + buf * FBUF;
            const uint32_t bVf = bKf + 8192;

            // ---- S = Q K^T (fp16), log2 scale ----
            float s[8][4] = {};
            #pragma unroll
            for (int ks = 0; ks < 4; ks++) {
                #pragma unroll
                for (int ntp = 0; ntp < 4; ntp++) {
                    int mat  = lane >> 3;
                    int key  = ntp * 16 + (mat >> 1) * 8 + (lane & 7);
                    int ch   = 2 * ks + (mat & 1);
                    uint32_t off = key * 128 + (((ch ^ (key & 7))) << 4);
                    uint32_t kf[4];
                    ldmx4(kf, bKf + off);
                    mma_fp16(s[2*ntp],   Qa[ks], kf);
                    mma_fp16(s[2*ntp+1], Qa[ks], kf + 2);
                }
            }

            // ---- causal mask (safe finite mask value; no clamp in exp) ----
            if ((kt << 6) + 63 > wq) {
                int q0 = wq + (lane >> 2), q1 = q0 + 8;
                #pragma unroll
                for (int nt = 0; nt < 8; nt++) {
                    int key = (kt << 6) + nt * 8 + ((lane & 3) << 1);
                    if (key     > q0) s[nt][0] = MASKVAL;
                    if (key + 1 > q0) s[nt][1] = MASKVAL;
                    if (key     > q1) s[nt][2] = MASKVAL;
                    if (key + 1 > q1) s[nt][3] = MASKVAL;
                }
            }

            // ---- p = exp2(s), lane-local sums ----
            #pragma unroll
            for (int nt = 0; nt < 8; nt++) {
                float p0 = exp2p(s[nt][0]);
                float p1 = exp2p(s[nt][1]);
                float p2 = exp2p(s[nt][2]);
                float p3 = exp2p(s[nt][3]);
                s[nt][0] = p0; s[nt][1] = p1; s[nt][2] = p2; s[nt][3] = p3;
                l0 += p0 + p1;
                l1 += p2 + p3;
            }

            // ---- O += P V (fp16) ----
            #pragma unroll
            for (int ks = 0; ks < 4; ks++) {
                uint32_t Pf[4];
                Pf[0] = h2pack(s[2*ks][0],   s[2*ks][1]);
                Pf[1] = h2pack(s[2*ks][2],   s[2*ks][3]);
                Pf[2] = h2pack(s[2*ks+1][0], s[2*ks+1][1]);
                Pf[3] = h2pack(s[2*ks+1][2], s[2*ks+1][3]);
                #pragma unroll
                for (int ntp = 0; ntp < 4; ntp++) {
                    int mat = lane >> 3;
                    int kk  = ks * 16 + (mat & 1) * 8 + (lane & 7);
                    int ch  = ntp * 2 + (mat >> 1);
                    uint32_t off = kk * 128 + (((ch ^ (kk & 7))) << 4);
                    uint32_t vf[4];
                    ldmx4t(vf, bVf + off);
                    mma_fp16(o[2*ntp],   Pf, vf);
                    mma_fp16(o[2*ntp+1], Pf, vf + 2);
                }
            }
        }
        __syncthreads();
    }

    l0 += __shfl_xor_sync(0xffffffffu, l0, 1);
    l0 += __shfl_xor_sync(0xffffffffu, l0, 2);
    l1 += __shfl_xor_sync(0xffffffffu, l1, 1);
    l1 += __shfl_xor_sync(0xffffffffu, l1, 2);

    const int b = bh >> 4, hdh = bh & 15;
    const int q0 = wq + (lane >> 2), q1 = q0 + 8;
    float inv0 = 1.0f / l0, inv1 = 1.0f / l1;
    #pragma unroll
    for (int nt = 0; nt < 8; nt++) {
        int d = nt * 8 + ((lane & 3) << 1);
        size_t o0 = (size_t)(b * LL + q0) * DD + hdh * 64 + d;
        size_t o1 = (size_t)(b * LL + q1) * DD + hdh * 64 + d;
        *(uint32_t*)&ctxf[o0] = h2pack(o[nt][0] * inv0, o[nt][1] * inv0);
        *(uint32_t*)&ctxf[o1] = h2pack(o[nt][2] * inv1, o[nt][3] * inv1);
    }
}

// ---------------------------------------------------------------------------
extern "C" void kernel_launch(void* const* d_in, const int* in_sizes, int n_in,
                              void* d_out, int out_size)
{
    const float* x      = (const float*)d_in[0];
    // d_in[1] = causal mask (tril) — causality applied analytically, unused
    const float* Wq     = (const float*)d_in[2];
    const float* Wk     = (const float*)d_in[3];
    const float* Wv     = (const float*)d_in[4];
    const float* Wo     = (const float*)d_in[5];
    const float* qgamma = (const float*)d_in[6];
    const float* qbeta  = (const float*)d_in[7];
    const float* kgamma = (const float*)d_in[8];
    const float* kbeta  = (const float*)d_in[9];
    float* out = (float*)d_out;

    __half *dxf, *dWq16, *dWk16, *dWv16, *dWo16, *dCf, *dVf, *dQf, *dKf;
    cudaGetSymbolAddress((void**)&dxf, g_xf);
    cudaGetSymbolAddress((void**)&dCf, g_Cf);
    cudaGetSymbolAddress((void**)&dVf, g_Vf);
    cudaGetSymbolAddress((void**)&dQf, g_Qf);
    cudaGetSymbolAddress((void**)&dKf, g_Kf);
    cudaGetSymbolAddress((void**)&dWq16, g_Wq16);
    cudaGetSymbolAddress((void**)&dWk16, g_Wk16);
    cudaGetSymbolAddress((void**)&dWv16, g_Wv16);
    cudaGetSymbolAddress((void**)&dWo16, g_Wo16);

    const int gemm_smem  = 2 * GBUF;   // 64 KB
    const int flash_smem = 2 * FBUF;   // 32 KB
    cudaFuncSetAttribute(gemm_qkv,
                         cudaFuncAttributeMaxDynamicSharedMemorySize, gemm_smem);
    cudaFuncSetAttribute(gemm_out,
                         cudaFuncAttributeMaxDynamicSharedMemorySize, gemm_smem);
    cudaFuncSetAttribute(flash_mma,
                         cudaFuncAttributeMaxDynamicSharedMemorySize, flash_smem);

    // fp16 operand conversion
    tohalf<<<NEL / 1024, 256>>>(x, dxf);
    tohalf_w4<<<4 * (DD * DD / 1024), 256>>>(Wq, Wk, Wv, Wo,
                                             dWq16, dWk16, dWv16, dWo16);

    // fused QKV projection + LN (one launch, 1536 CTAs)
    gemm_qkv<<<dim3(24, NTOK / 128), 128, gemm_smem>>>(
        dxf, dWq16, dWk16, dWv16, dQf, dKf, dVf,
        qgamma, qbeta, kgamma, kbeta);

    flash_mma<<<dim3(BB * HH, LL / 128), 256, flash_smem>>>(dQf, dKf, dVf, dCf);

    gemm_out<<<dim3(DD / 128, NTOK / 128), 128, gemm_smem>>>(dCf, dWo16, out);
}